// round 12
// baseline (speedup 1.0000x reference)
#include <cuda_runtime.h>
#include <cuda_fp16.h>
#include <mma.h>
#include <math.h>

using namespace nvcuda;

#define NN 100000
#define EE 1600000
#define HH 64
#define XS_LD 80   // padded smem stride (halves / floats)

typedef unsigned long long u64;

// ---------------- scratch (device globals) ----------------------------------
__device__ __half g_x16[(size_t)NN * HH];    // x converted to fp16
__device__ __half g_y[2 * (size_t)NN * HH];  // GEMM outputs (fp16)
__device__ __half g_h[2 * (size_t)NN * HH];  // layer-1 activations (fp16)
__device__ float  g_norms[4 * NN];           // csp | cdp | csn | cdn
__device__ int    g_cnt[4 * NN];             // int degree counts (same layout)
__device__ int    g_off[2 * (NN + 1)];       // CSR row offsets (dst) per relation
__device__ int    g_rank[2 * (size_t)EE];    // per-edge rank within dst bucket
__device__ int    g_csr[2 * EE];             // src ids grouped by dst
__device__ int    g_flag[2 * 128];           // lookback flags (0/1/2)
__device__ int    g_pval[2 * 128];           // block partial sums
__device__ int    g_ival[2 * 128];           // block inclusive prefixes
__device__ float  g_proj[4 * NN];            // classifier projections [N][4]

// ---------------- prep: zero counts + lookback flags only --------------------
__global__ void prep_kernel(int4* __restrict__ cnt4, int* __restrict__ flag, int n) {
    int t = blockIdx.x * blockDim.x + threadIdx.x;
    if (t < n) cnt4[t] = make_int4(0, 0, 0, 0);
    else if (t < n + 256) flag[t - n] = 0;
}

// ---------------- degrees (+rank on dst passes) + x16 conversion (w==4) ------
__global__ void deg4_kernel(const int* __restrict__ sp, const int* __restrict__ dp,
                            const int* __restrict__ sn, const int* __restrict__ dn,
                            int* __restrict__ cnt, int* __restrict__ rank,
                            const float* __restrict__ x, __half* __restrict__ x16,
                            int n, int nE, int nx4) {
    int t = blockIdx.x * blockDim.x + threadIdx.x;
    int w = blockIdx.y;
    if (w == 4) {                       // x fp32 -> fp16 (independent work)
        if (t < nx4) {
            float4 v = ((const float4*)x)[t];
            __half2 h[2] = {__floats2half2_rn(v.x, v.y), __floats2half2_rn(v.z, v.w)};
            ((uint2*)x16)[t] = *(const uint2*)h;
        }
        return;
    }
    if (t >= nE) return;
    if (w == 0)      atomicAdd(cnt + sp[t], 1);
    else if (w == 2) atomicAdd(cnt + 2 * (size_t)n + sn[t], 1);
    else if (w == 1) rank[t] = atomicAdd(cnt + (size_t)n + dp[t], 1);
    else             rank[(size_t)EE + t] = atomicAdd(cnt + 3 * (size_t)n + dn[t], 1);
}

// ---------------- one-launch scan: norms (all 4) + CSR offsets (lookback) ----
__global__ void scan_lb_norm(const int* __restrict__ cnt, float* __restrict__ norms,
                             volatile int* flag, volatile int* pval, volatile int* ival,
                             int* __restrict__ offv, int n, int nEp, int nEn) {
    int w = blockIdx.y;                 // 0..3
    int bx = blockIdx.x;
    int tid = threadIdx.x;
    const int* c = cnt + (size_t)w * n;
    float* nm = norms + (size_t)w * n;
    int base = bx * 1024 + tid * 4;

    int v[4], s = 0;
    #pragma unroll
    for (int j = 0; j < 4; j++) {
        int i = base + j;
        v[j] = (i < n) ? c[i] : 0;
        s += v[j];
        if (i < n) nm[i] = (v[j] > 0) ? rsqrtf((float)v[j]) : 0.f;
    }
    if (!(w & 1)) return;               // only dst arrays build CSR
    int rel = w >> 1;
    int sbase = rel * 128;

    __shared__ int sm[256];
    sm[tid] = s; __syncthreads();
    for (int ofs = 1; ofs < 256; ofs <<= 1) {
        int a = (tid >= ofs) ? sm[tid - ofs] : 0;
        __syncthreads();
        sm[tid] += a;
        __syncthreads();
    }
    int excl = sm[tid] - s;
    int bsum = sm[255];

    __shared__ int bprefix;
    if (tid == 0) {
        pval[sbase + bx] = bsum;
        __threadfence();
        flag[sbase + bx] = 1;
        int pref = 0;
        for (int p = bx - 1; p >= 0; ) {
            int f;
            do { f = flag[sbase + p]; } while (f == 0);
            if (f == 2) { pref += ival[sbase + p]; break; }
            pref += pval[sbase + p];
            p--;
        }
        ival[sbase + bx] = pref + bsum;
        __threadfence();
        flag[sbase + bx] = 2;
        bprefix = pref;
    }
    __syncthreads();

    int ex = bprefix + excl;
    int* o = offv + (size_t)rel * (n + 1);
    #pragma unroll
    for (int j = 0; j < 4; j++) {
        int i = base + j;
        if (i < n) o[i] = ex;
        ex += v[j];
    }
    if (bx == 0 && tid == 0) o[n] = rel ? nEn : nEp;
}

// ---------------- wmma GEMM body, 30 KB smem, two-phase epilogue -------------
// sbuf: [ Wh 64*XS_LD halves | Xh 128*XS_LD halves ]; Os (64 rows fp32) = Xh.
__device__ __forceinline__ void gemm_body(const __half* __restrict__ X,
                                          const float* __restrict__ cs,
                                          const float* __restrict__ W,
                                          __half* __restrict__ Yo, int n, int blk) {
    __shared__ __align__(16) __half sbuf[192 * XS_LD];   // 30720 B
    __half* Wh = sbuf;
    __half* Xh = sbuf + 64 * XS_LD;
    float*  Os = (float*)Xh;            // 64 rows x XS_LD floats, reused post-MMA

    int tid = threadIdx.x;
    int row0 = blk * 128;

    for (int i = tid; i < 2048; i += 256) {
        int k = i >> 5, j = i & 31;
        float2 v = ((const float2*)W)[(size_t)k * 32 + j];
        *(__half2*)&Wh[k * XS_LD + 2 * j] = __floats2half2_rn(v.x, v.y);
    }
    for (int i = tid; i < 2048; i += 256) {
        int r = i >> 4, kq = i & 15;
        int gr = row0 + r;
        uint2 v2 = (gr < n) ? __ldg((const uint2*)X + (size_t)gr * 16 + kq)
                            : make_uint2(0, 0);
        *(uint2*)&Xh[r * XS_LD + 4 * kq] = v2;
    }
    __syncthreads();

    int w = tid >> 5;
    wmma::fragment<wmma::accumulator, 16, 16, 16, float> acc[4];
    #pragma unroll
    for (int t = 0; t < 4; t++) wmma::fill_fragment(acc[t], 0.f);
    #pragma unroll
    for (int k = 0; k < 64; k += 16) {
        wmma::fragment<wmma::matrix_a, 16, 16, 16, __half, wmma::row_major> a;
        wmma::load_matrix_sync(a, &Xh[(w * 16) * XS_LD + k], XS_LD);
        #pragma unroll
        for (int t = 0; t < 4; t++) {
            wmma::fragment<wmma::matrix_b, 16, 16, 16, __half, wmma::row_major> b;
            wmma::load_matrix_sync(b, &Wh[k * XS_LD + t * 16], XS_LD);
            wmma::mma_sync(acc[t], a, b, acc[t]);
        }
    }
    __syncthreads();                    // all Wh/Xh reads done

    // two-phase epilogue: rows [0,64) then [64,128), staging 64 rows in Os
    #pragma unroll
    for (int ph = 0; ph < 2; ph++) {
        if ((w >> 2) == ph) {           // warps owning this half store their acc
            int rloc = (w & 3) * 16;
            #pragma unroll
            for (int t = 0; t < 4; t++)
                wmma::store_matrix_sync(&Os[rloc * XS_LD + t * 16], acc[t], XS_LD,
                                        wmma::mem_row_major);
        }
        __syncthreads();
        for (int i = tid; i < 1024; i += 256) {
            int r = i >> 4, q = i & 15;
            int gr = row0 + ph * 64 + r;
            if (gr < n) {
                float c = cs[gr];
                float4 v = *(const float4*)&Os[r * XS_LD + 4 * q];
                __half2 o[2] = {__floats2half2_rn(v.x * c, v.y * c),
                                __floats2half2_rn(v.z * c, v.w * c)};
                *(uint2*)(Yo + (size_t)gr * 64 + 4 * q) = *(const uint2*)o;
            }
        }
        __syncthreads();
    }
}

// ---------------- fat kernel: layer-1 GEMM (both rels) + atomic-free scatter -
__global__ void __launch_bounds__(256, 6)
gemm1_scatter(const __half* __restrict__ x16, const float* __restrict__ norms,
              const float* __restrict__ W0, const float* __restrict__ W1,
              __half* __restrict__ Y,
              const int* __restrict__ srcp, const int* __restrict__ dstp,
              const int* __restrict__ srcn, const int* __restrict__ dstn,
              const int* __restrict__ off, const int* __restrict__ rank,
              int* __restrict__ csr,
              int n, int nEp, int nEn, int gGemm, int gScat) {
    int b = blockIdx.x;
    if (b < 2 * gGemm) {
        int rel = b / gGemm;
        gemm_body(x16, norms + 2 * (size_t)rel * n,
                  rel ? W1 : W0, Y + (size_t)rel * n * 64, n, b % gGemm);
    } else {
        int sb = b - 2 * gGemm;
        int rel = sb / gScat;
        int e = (sb % gScat) * 256 + threadIdx.x;
        int nE = rel ? nEn : nEp;
        if (e >= nE) return;
        const int* src = rel ? srcn : srcp;
        const int* dst = rel ? dstn : dstp;
        int d = dst[e];
        int p = __ldg(off + (size_t)rel * (n + 1) + d) + rank[(size_t)rel * EE + e];
        csr[(size_t)rel * EE + p] = src[e];
    }
}

// ---------------- layer-2 GEMM (fp16 input) ----------------------------------
__global__ void __launch_bounds__(256, 6)
gemm_l2(const __half* __restrict__ h, const float* __restrict__ norms,
        const float* __restrict__ W0, const float* __restrict__ W1,
        __half* __restrict__ Y, int n) {
    int rel = blockIdx.y;
    gemm_body(h + (size_t)rel * n * 64, norms + 2 * (size_t)rel * n,
              rel ? W1 : W0, Y + (size_t)rel * n * 64, n, blockIdx.x);
}

// ---------------- CSR pull (fp16 payload, fp32 accum, MLP=4) -----------------
__device__ __forceinline__ float2 csr_sum(const int* __restrict__ off,
                                          const int* __restrict__ csr,
                                          const __half2* __restrict__ ylane, int node) {
    int j = off[node], end = off[node + 1];
    float2 a0 = make_float2(0.f, 0.f), a1 = make_float2(0.f, 0.f);
    float2 a2 = make_float2(0.f, 0.f), a3 = make_float2(0.f, 0.f);
    for (; j + 4 <= end; j += 4) {
        int s0 = __ldg(csr + j + 0);
        int s1 = __ldg(csr + j + 1);
        int s2 = __ldg(csr + j + 2);
        int s3 = __ldg(csr + j + 3);
        __half2 h0 = __ldg(ylane + (size_t)s0 * 32);
        __half2 h1 = __ldg(ylane + (size_t)s1 * 32);
        __half2 h2 = __ldg(ylane + (size_t)s2 * 32);
        __half2 h3 = __ldg(ylane + (size_t)s3 * 32);
        float2 v0 = __half22float2(h0); a0.x += v0.x; a0.y += v0.y;
        float2 v1 = __half22float2(h1); a1.x += v1.x; a1.y += v1.y;
        float2 v2 = __half22float2(h2); a2.x += v2.x; a2.y += v2.y;
        float2 v3 = __half22float2(h3); a3.x += v3.x; a3.y += v3.y;
    }
    for (; j < end; j++) {
        int s = __ldg(csr + j);
        float2 v = __half22float2(__ldg(ylane + (size_t)s * 32));
        a0.x += v.x; a0.y += v.y;
    }
    a0.x += a1.x; a0.y += a1.y;
    a2.x += a3.x; a2.y += a3.y;
    a0.x += a2.x; a0.y += a2.y;
    return a0;
}

// layer 1: h_rel[i,:] = half(relu(c_dst[i] * sum y_rel[src] + b0_rel))
__global__ void agg_l1(const __half* __restrict__ y, const int* __restrict__ off,
                       const int* __restrict__ csr, const float* __restrict__ norms,
                       const float* __restrict__ b0p, const float* __restrict__ b0n,
                       __half* __restrict__ h, int n) {
    int rel = blockIdx.y;
    int node = blockIdx.x * 8 + (threadIdx.x >> 5);
    if (node >= n) return;
    int lane = threadIdx.x & 31;
    const __half2* yl = (const __half2*)(y + (size_t)rel * n * 64) + lane;
    float2 a = csr_sum(off + (size_t)rel * (n + 1), csr + (size_t)rel * EE, yl, node);
    float c = norms[(size_t)(1 + 2 * rel) * n + node];
    const float* b = rel ? b0n : b0p;
    float rx = fmaxf(c * a.x + b[2 * lane + 0], 0.f);
    float ry = fmaxf(c * a.y + b[2 * lane + 1], 0.f);
    ((__half2*)(h + (size_t)rel * n * 64 + (size_t)node * 64))[lane] =
        __floats2half2_rn(rx, ry);
}

// layer 2 agg fused: z = relu(cdp*sumP + b1p) - relu(cdn*sumN + b1n) + proj
__global__ void agg_l2(const __half* __restrict__ y, const int* __restrict__ off,
                       const int* __restrict__ csr, const float* __restrict__ norms,
                       const float* __restrict__ b1p, const float* __restrict__ b1n,
                       const float* __restrict__ Wc,
                       float* __restrict__ z, float* __restrict__ proj, int n) {
    __shared__ float Wcs[256];
    Wcs[threadIdx.x] = Wc[threadIdx.x];   // blockDim == 256
    __syncthreads();

    int node = blockIdx.x * 8 + (threadIdx.x >> 5);
    if (node >= n) return;
    int lane = threadIdx.x & 31;
    const __half2* ylP = (const __half2*)y + lane;
    const __half2* ylN = (const __half2*)(y + (size_t)n * 64) + lane;
    float2 aP = csr_sum(off, csr, ylP, node);
    float2 aN = csr_sum(off + (n + 1), csr + (size_t)EE, ylN, node);
    float cp = norms[(size_t)n + node];
    float cn = norms[3 * (size_t)n + node];
    float2 r;
    r.x = fmaxf(cp * aP.x + b1p[2 * lane + 0], 0.f) - fmaxf(cn * aN.x + b1n[2 * lane + 0], 0.f);
    r.y = fmaxf(cp * aP.y + b1p[2 * lane + 1], 0.f) - fmaxf(cn * aN.y + b1n[2 * lane + 1], 0.f);
    *(float2*)(z + (size_t)node * 64 + lane * 2) = r;

    int k = 2 * lane;
    float s0 = r.x * Wcs[k * 2 + 0] + r.y * Wcs[(k + 1) * 2 + 0];
    float s1 = r.x * Wcs[k * 2 + 1] + r.y * Wcs[(k + 1) * 2 + 1];
    float d0 = r.x * Wcs[128 + k * 2 + 0] + r.y * Wcs[128 + (k + 1) * 2 + 0];
    float d1 = r.x * Wcs[128 + k * 2 + 1] + r.y * Wcs[128 + (k + 1) * 2 + 1];
    #pragma unroll
    for (int o = 16; o > 0; o >>= 1) {
        s0 += __shfl_xor_sync(0xffffffffu, s0, o);
        s1 += __shfl_xor_sync(0xffffffffu, s1, o);
        d0 += __shfl_xor_sync(0xffffffffu, d0, o);
        d1 += __shfl_xor_sync(0xffffffffu, d1, o);
    }
    if (lane == 0) ((float4*)proj)[node] = make_float4(s0, s1, d0, d1);
}

// ---------------- classifier --------------------------------------------------
__global__ void cls_kernel(const float* __restrict__ p, const int* __restrict__ ei,
                           const float* __restrict__ bc, float* __restrict__ out, int nQ) {
    int q = blockIdx.x * blockDim.x + threadIdx.x;
    if (q >= nQ) return;
    int s = __ldg(ei + q);
    int d = __ldg(ei + nQ + q);
    float4 ps = ((const float4*)p)[s];
    float4 pd = ((const float4*)p)[d];
    float l0 = ps.x + pd.z + bc[0];
    float l1 = ps.y + pd.w + bc[1];
    float2 o;
    o.x = 1.f / (1.f + __expf(-l0));
    o.y = 1.f / (1.f + __expf(-l1));
    ((float2*)out)[q] = o;
}

// ---------------- launch -------------------------------------------------------
static inline int cdiv(long long a, int b) { return (int)((a + b - 1) / b); }

extern "C" void kernel_launch(void* const* d_in, const int* in_sizes, int n_in,
                              void* d_out, int out_size) {
    const float* x    = (const float*)d_in[0];
    const float* W0p  = (const float*)d_in[1];
    const float* b0p  = (const float*)d_in[2];
    const float* W0n  = (const float*)d_in[3];
    const float* b0n  = (const float*)d_in[4];
    const float* W1p  = (const float*)d_in[5];
    const float* b1p  = (const float*)d_in[6];
    const float* W1n  = (const float*)d_in[7];
    const float* b1n  = (const float*)d_in[8];
    const float* Wc   = (const float*)d_in[9];
    const float* bc   = (const float*)d_in[10];
    const int*   srcp = (const int*)d_in[11];
    const int*   dstp = (const int*)d_in[12];
    const int*   srcn = (const int*)d_in[13];
    const int*   dstn = (const int*)d_in[14];
    const int*   ei   = (const int*)d_in[15];

    const int n   = in_sizes[0] / HH;
    const int nEp = in_sizes[11];
    const int nEn = in_sizes[13];
    const int nQ  = in_sizes[15] / 2;

    __half *x16, *y, *h;
    float *norms, *pbuf;
    int *cnt, *off, *rank, *csr, *flag, *pval, *ival;
    cudaGetSymbolAddress((void**)&x16,   g_x16);
    cudaGetSymbolAddress((void**)&y,     g_y);
    cudaGetSymbolAddress((void**)&h,     g_h);
    cudaGetSymbolAddress((void**)&norms, g_norms);
    cudaGetSymbolAddress((void**)&cnt,   g_cnt);
    cudaGetSymbolAddress((void**)&off,   g_off);
    cudaGetSymbolAddress((void**)&rank,  g_rank);
    cudaGetSymbolAddress((void**)&csr,   g_csr);
    cudaGetSymbolAddress((void**)&flag,  g_flag);
    cudaGetSymbolAddress((void**)&pval,  g_pval);
    cudaGetSymbolAddress((void**)&ival,  g_ival);
    cudaGetSymbolAddress((void**)&pbuf,  g_proj);

    float* z     = (float*)d_out;
    float* probs = (float*)d_out + (size_t)n * HH;

    const int nb    = cdiv(n, 1024);              // 98 (<=128)
    const int nx4   = n * 16;                     // float4 chunks of x
    const int gGemm = cdiv(n, 128);
    const int gScat = cdiv(nEp > nEn ? nEp : nEn, 256);
    const int gDeg  = cdiv(nEp > nx4 ? nEp : nx4, 256);
    const int gAgg  = cdiv(n, 8);

    // 1) zero counts + lookback flags
    prep_kernel<<<cdiv(n + 256, 256), 256>>>((int4*)cnt, flag, n);
    // 2) degrees (+rank) overlapped with x -> fp16 conversion
    deg4_kernel<<<dim3(gDeg, 5), 256>>>(srcp, dstp, srcn, dstn, cnt, rank,
                                        x, x16, n, nEp, nx4);
    // 3) norms + CSR offsets in one launch (decoupled lookback)
    scan_lb_norm<<<dim3(nb, 4), 256>>>(cnt, norms, flag, pval, ival, off,
                                       n, nEp, nEn);
    // 4) layer-1 GEMM (tensor cores, fp16 x) + atomic-free CSR scatter
    gemm1_scatter<<<2 * gGemm + 2 * gScat, 256>>>(
        x16, norms, W0p, W0n, y, srcp, dstp, srcn, dstn, off, rank, csr,
        n, nEp, nEn, gGemm, gScat);
    // 5) layer-1 aggregation -> h (fp16), full occupancy
    agg_l1<<<dim3(gAgg, 2), 256>>>(y, off, csr, norms, b0p, b0n, h, n);
    // 6) layer-2 GEMM (fp16 input, tensor cores)
    gemm_l2<<<dim3(gGemm, 2), 256>>>(h, norms, W1p, W1n, y, n);
    // 7) layer-2 aggregation + combine + classifier projection
    agg_l2<<<gAgg, 256>>>(y, off, csr, norms, b1p, b1n, Wc, z, pbuf, n);
    // 8) classifier
    cls_kernel<<<cdiv(nQ, 256), 256>>>(pbuf, ei, bc, probs, nQ);
}

// round 13
// speedup vs baseline: 1.0340x; 1.0340x over previous
#include <cuda_runtime.h>
#include <cuda_fp16.h>
#include <mma.h>
#include <math.h>

using namespace nvcuda;

#define NN 100000
#define EE 1600000
#define HH 64
#define XS_LD 80   // padded smem stride (halves / floats)

typedef unsigned long long u64;

// ---------------- scratch (device globals) ----------------------------------
__device__ __half g_x16[(size_t)NN * HH];    // x converted to fp16
__device__ __half g_y[2 * (size_t)NN * HH];  // GEMM outputs (fp16)
__device__ __half g_h[2 * (size_t)NN * HH];  // layer-1 activations (fp16)
__device__ float  g_norms[4 * NN];           // csp | cdp | csn | cdn
__device__ int    g_cnt[4 * NN];             // int degree counts (same layout)
__device__ int    g_off[2 * (NN + 1)];       // CSR row offsets (dst) per relation
__device__ int    g_rank[2 * (size_t)EE];    // per-edge rank within dst bucket
__device__ int    g_csr[2 * EE];             // src ids grouped by dst
__device__ int    g_flag[2 * 128];           // lookback flags (0/1/2)
__device__ int    g_pval[2 * 128];           // block partial sums
__device__ int    g_ival[2 * 128];           // block inclusive prefixes
__device__ float  g_proj[4 * NN];            // classifier projections [N][4]

// ---------------- prep: zero counts+flags, convert x -> fp16 -----------------
__global__ void prep_kernel(const float* __restrict__ x, int4* __restrict__ cnt4,
                            int* __restrict__ flag, __half* __restrict__ x16,
                            int n, int nx4) {
    int t = blockIdx.x * blockDim.x + threadIdx.x;
    if (t < n) { cnt4[t] = make_int4(0, 0, 0, 0); return; }
    if (t < n + 256) { flag[t - n] = 0; return; }
    int c = t - (n + 256);
    if (c < nx4) {
        float4 v = ((const float4*)x)[c];
        __half2 h[2] = {__floats2half2_rn(v.x, v.y), __floats2half2_rn(v.z, v.w)};
        ((uint2*)x16)[c] = *(const uint2*)h;
    }
}

// ---------------- degrees; dst passes also record per-edge rank --------------
__global__ void deg4_kernel(const int* __restrict__ sp, const int* __restrict__ dp,
                            const int* __restrict__ sn, const int* __restrict__ dn,
                            int* __restrict__ cnt, int* __restrict__ rank,
                            int n, int nE) {
    int t = blockIdx.x * blockDim.x + threadIdx.x;
    if (t >= nE) return;
    int w = blockIdx.y;
    if (w == 0)      atomicAdd(cnt + sp[t], 1);
    else if (w == 2) atomicAdd(cnt + 2 * (size_t)n + sn[t], 1);
    else if (w == 1) rank[t] = atomicAdd(cnt + (size_t)n + dp[t], 1);
    else             rank[(size_t)EE + t] = atomicAdd(cnt + 3 * (size_t)n + dn[t], 1);
}

// ---------------- one-launch scan: norms (all 4) + CSR offsets (lookback) ----
__global__ void scan_lb_norm(const int* __restrict__ cnt, float* __restrict__ norms,
                             volatile int* flag, volatile int* pval, volatile int* ival,
                             int* __restrict__ offv, int n, int nEp, int nEn) {
    int w = blockIdx.y;                 // 0..3
    int bx = blockIdx.x;
    int tid = threadIdx.x;
    const int* c = cnt + (size_t)w * n;
    float* nm = norms + (size_t)w * n;
    int base = bx * 1024 + tid * 4;

    int v[4], s = 0;
    #pragma unroll
    for (int j = 0; j < 4; j++) {
        int i = base + j;
        v[j] = (i < n) ? c[i] : 0;
        s += v[j];
        if (i < n) nm[i] = (v[j] > 0) ? rsqrtf((float)v[j]) : 0.f;
    }
    if (!(w & 1)) return;               // only dst arrays build CSR
    int rel = w >> 1;
    int sbase = rel * 128;

    __shared__ int sm[256];
    sm[tid] = s; __syncthreads();
    for (int ofs = 1; ofs < 256; ofs <<= 1) {
        int a = (tid >= ofs) ? sm[tid - ofs] : 0;
        __syncthreads();
        sm[tid] += a;
        __syncthreads();
    }
    int excl = sm[tid] - s;
    int bsum = sm[255];

    __shared__ int bprefix;
    if (tid == 0) {
        pval[sbase + bx] = bsum;
        __threadfence();
        flag[sbase + bx] = 1;
        int pref = 0;
        for (int p = bx - 1; p >= 0; ) {
            int f;
            do { f = flag[sbase + p]; } while (f == 0);
            if (f == 2) { pref += ival[sbase + p]; break; }
            pref += pval[sbase + p];
            p--;
        }
        ival[sbase + bx] = pref + bsum;
        __threadfence();
        flag[sbase + bx] = 2;
        bprefix = pref;
    }
    __syncthreads();

    int ex = bprefix + excl;
    int* o = offv + (size_t)rel * (n + 1);
    #pragma unroll
    for (int j = 0; j < 4; j++) {
        int i = base + j;
        if (i < n) o[i] = ex;
        ex += v[j];
    }
    if (bx == 0 && tid == 0) o[n] = rel ? nEn : nEp;
}

// ---------------- wmma GEMM body (fp16 input), smem union (40 KB) ------------
__device__ __forceinline__ void gemm_body(const __half* __restrict__ X,
                                          const float* __restrict__ cs,
                                          const float* __restrict__ W,
                                          __half* __restrict__ Yo, int n, int blk) {
    __shared__ __align__(16) float sbuf[128 * XS_LD];   // 40960 B
    __half* Wh = (__half*)sbuf;
    __half* Xh = ((__half*)sbuf) + 64 * XS_LD;
    float*  Os = sbuf;                                  // reused after MMA

    int tid = threadIdx.x;
    int row0 = blk * 128;

    for (int i = tid; i < 2048; i += 256) {
        int k = i >> 5, j = i & 31;
        float2 v = ((const float2*)W)[(size_t)k * 32 + j];
        *(__half2*)&Wh[k * XS_LD + 2 * j] = __floats2half2_rn(v.x, v.y);
    }
    for (int i = tid; i < 2048; i += 256) {
        int r = i >> 4, kq = i & 15;
        int gr = row0 + r;
        uint2 v2 = (gr < n) ? __ldg((const uint2*)X + (size_t)gr * 16 + kq)
                            : make_uint2(0, 0);
        *(uint2*)&Xh[r * XS_LD + 4 * kq] = v2;
    }
    __syncthreads();

    int w = tid >> 5;
    wmma::fragment<wmma::accumulator, 16, 16, 16, float> acc[4];
    #pragma unroll
    for (int t = 0; t < 4; t++) wmma::fill_fragment(acc[t], 0.f);
    #pragma unroll
    for (int k = 0; k < 64; k += 16) {
        wmma::fragment<wmma::matrix_a, 16, 16, 16, __half, wmma::row_major> a;
        wmma::load_matrix_sync(a, &Xh[(w * 16) * XS_LD + k], XS_LD);
        #pragma unroll
        for (int t = 0; t < 4; t++) {
            wmma::fragment<wmma::matrix_b, 16, 16, 16, __half, wmma::row_major> b;
            wmma::load_matrix_sync(b, &Wh[k * XS_LD + t * 16], XS_LD);
            wmma::mma_sync(acc[t], a, b, acc[t]);
        }
    }
    __syncthreads();             // all reads of Wh/Xh done; Os may overwrite
    #pragma unroll
    for (int t = 0; t < 4; t++)
        wmma::store_matrix_sync(&Os[(w * 16) * XS_LD + t * 16], acc[t], XS_LD,
                                wmma::mem_row_major);
    __syncthreads();

    for (int i = tid; i < 2048; i += 256) {
        int r = i >> 4, q = i & 15;
        int gr = row0 + r;
        if (gr >= n) continue;
        float c = cs[gr];
        float4 v = *(const float4*)&Os[r * XS_LD + 4 * q];
        __half2 o[2] = {__floats2half2_rn(v.x * c, v.y * c),
                        __floats2half2_rn(v.z * c, v.w * c)};
        *(uint2*)(Yo + (size_t)gr * 64 + 4 * q) = *(const uint2*)o;
    }
}

// ---------------- fat kernel: layer-1 GEMM (both rels) + atomic-free scatter -
__global__ void __launch_bounds__(256, 4)
gemm1_scatter(const __half* __restrict__ x16, const float* __restrict__ norms,
              const float* __restrict__ W0, const float* __restrict__ W1,
              __half* __restrict__ Y,
              const int* __restrict__ srcp, const int* __restrict__ dstp,
              const int* __restrict__ srcn, const int* __restrict__ dstn,
              const int* __restrict__ off, const int* __restrict__ rank,
              int* __restrict__ csr,
              int n, int nEp, int nEn, int gGemm, int gScat) {
    int b = blockIdx.x;
    if (b < 2 * gGemm) {
        int rel = b / gGemm;
        gemm_body(x16, norms + 2 * (size_t)rel * n,
                  rel ? W1 : W0, Y + (size_t)rel * n * 64, n, b % gGemm);
    } else {
        int sb = b - 2 * gGemm;
        int rel = sb / gScat;
        int e = (sb % gScat) * 256 + threadIdx.x;
        int nE = rel ? nEn : nEp;
        if (e >= nE) return;
        const int* src = rel ? srcn : srcp;
        const int* dst = rel ? dstn : dstp;
        int d = dst[e];
        int p = __ldg(off + (size_t)rel * (n + 1) + d) + rank[(size_t)rel * EE + e];
        csr[(size_t)rel * EE + p] = src[e];
    }
}

// ---------------- layer-2 GEMM (fp16 input) ----------------------------------
__global__ void __launch_bounds__(256, 4)
gemm_l2(const __half* __restrict__ h, const float* __restrict__ norms,
        const float* __restrict__ W0, const float* __restrict__ W1,
        __half* __restrict__ Y, int n) {
    int rel = blockIdx.y;
    gemm_body(h + (size_t)rel * n * 64, norms + 2 * (size_t)rel * n,
              rel ? W1 : W0, Y + (size_t)rel * n * 64, n, blockIdx.x);
}

// ---------------- dual-stream CSR pull: two independent idx->payload chains --
__device__ __forceinline__ void csr_sum_dual(
    const int* __restrict__ off0, const int* __restrict__ csr0,
    const __half2* __restrict__ yl0,
    const int* __restrict__ off1, const int* __restrict__ csr1,
    const __half2* __restrict__ yl1,
    int node, float2& r0, float2& r1) {
    int j0 = __ldg(off0 + node), e0 = __ldg(off0 + node + 1);
    int j1 = __ldg(off1 + node), e1 = __ldg(off1 + node + 1);
    float2 a00 = make_float2(0.f, 0.f), a01 = make_float2(0.f, 0.f);
    float2 a10 = make_float2(0.f, 0.f), a11 = make_float2(0.f, 0.f);

    // interleaved main loop: 4 independent idx loads + 4 independent gathers
    while (j0 + 2 <= e0 && j1 + 2 <= e1) {
        int sA = __ldg(csr0 + j0);
        int sB = __ldg(csr0 + j0 + 1);
        int sC = __ldg(csr1 + j1);
        int sD = __ldg(csr1 + j1 + 1);
        __half2 hA = __ldg(yl0 + (size_t)sA * 32);
        __half2 hB = __ldg(yl0 + (size_t)sB * 32);
        __half2 hC = __ldg(yl1 + (size_t)sC * 32);
        __half2 hD = __ldg(yl1 + (size_t)sD * 32);
        float2 vA = __half22float2(hA); a00.x += vA.x; a00.y += vA.y;
        float2 vB = __half22float2(hB); a01.x += vB.x; a01.y += vB.y;
        float2 vC = __half22float2(hC); a10.x += vC.x; a10.y += vC.y;
        float2 vD = __half22float2(hD); a11.x += vD.x; a11.y += vD.y;
        j0 += 2; j1 += 2;
    }
    // drain stream 0
    for (; j0 + 2 <= e0; j0 += 2) {
        int sA = __ldg(csr0 + j0);
        int sB = __ldg(csr0 + j0 + 1);
        __half2 hA = __ldg(yl0 + (size_t)sA * 32);
        __half2 hB = __ldg(yl0 + (size_t)sB * 32);
        float2 vA = __half22float2(hA); a00.x += vA.x; a00.y += vA.y;
        float2 vB = __half22float2(hB); a01.x += vB.x; a01.y += vB.y;
    }
    if (j0 < e0) {
        int sA = __ldg(csr0 + j0);
        float2 vA = __half22float2(__ldg(yl0 + (size_t)sA * 32));
        a00.x += vA.x; a00.y += vA.y;
    }
    // drain stream 1
    for (; j1 + 2 <= e1; j1 += 2) {
        int sC = __ldg(csr1 + j1);
        int sD = __ldg(csr1 + j1 + 1);
        __half2 hC = __ldg(yl1 + (size_t)sC * 32);
        __half2 hD = __ldg(yl1 + (size_t)sD * 32);
        float2 vC = __half22float2(hC); a10.x += vC.x; a10.y += vC.y;
        float2 vD = __half22float2(hD); a11.x += vD.x; a11.y += vD.y;
    }
    if (j1 < e1) {
        int sC = __ldg(csr1 + j1);
        float2 vC = __half22float2(__ldg(yl1 + (size_t)sC * 32));
        a10.x += vC.x; a10.y += vC.y;
    }
    r0 = make_float2(a00.x + a01.x, a00.y + a01.y);
    r1 = make_float2(a10.x + a11.x, a10.y + a11.y);
}

// layer 1, both relations per warp: h_rel[i,:] = half(relu(c_dst * sum + b0))
__global__ void agg_l1(const __half* __restrict__ y, const int* __restrict__ off,
                       const int* __restrict__ csr, const float* __restrict__ norms,
                       const float* __restrict__ b0p, const float* __restrict__ b0n,
                       __half* __restrict__ h, int n) {
    int node = blockIdx.x * 8 + (threadIdx.x >> 5);
    if (node >= n) return;
    int lane = threadIdx.x & 31;
    const __half2* yl0 = (const __half2*)y + lane;
    const __half2* yl1 = (const __half2*)(y + (size_t)n * 64) + lane;
    float2 aP, aN;
    csr_sum_dual(off, csr, yl0, off + (n + 1), csr + (size_t)EE, yl1, node, aP, aN);
    float c0 = norms[(size_t)n + node];
    float c1 = norms[3 * (size_t)n + node];
    float2 bp = *(const float2*)(b0p + 2 * lane);
    float2 bn = *(const float2*)(b0n + 2 * lane);
    ((__half2*)(h + (size_t)node * 64))[lane] =
        __floats2half2_rn(fmaxf(c0 * aP.x + bp.x, 0.f), fmaxf(c0 * aP.y + bp.y, 0.f));
    ((__half2*)(h + ((size_t)n + node) * 64))[lane] =
        __floats2half2_rn(fmaxf(c1 * aN.x + bn.x, 0.f), fmaxf(c1 * aN.y + bn.y, 0.f));
}

// layer 2: z = relu(cdp*sumP + b1p) - relu(cdn*sumN + b1n) + fused projection
__global__ void agg_l2(const __half* __restrict__ y, const int* __restrict__ off,
                       const int* __restrict__ csr, const float* __restrict__ norms,
                       const float* __restrict__ b1p, const float* __restrict__ b1n,
                       const float* __restrict__ Wc,
                       float* __restrict__ z, float* __restrict__ proj, int n) {
    __shared__ float Wcs[256];
    Wcs[threadIdx.x] = Wc[threadIdx.x];   // blockDim == 256
    __syncthreads();

    int node = blockIdx.x * 8 + (threadIdx.x >> 5);
    if (node >= n) return;
    int lane = threadIdx.x & 31;
    const __half2* yl0 = (const __half2*)y + lane;
    const __half2* yl1 = (const __half2*)(y + (size_t)n * 64) + lane;
    float2 aP, aN;
    csr_sum_dual(off, csr, yl0, off + (n + 1), csr + (size_t)EE, yl1, node, aP, aN);
    float cp = norms[(size_t)n + node];
    float cn = norms[3 * (size_t)n + node];
    float2 r;
    r.x = fmaxf(cp * aP.x + b1p[2 * lane + 0], 0.f) - fmaxf(cn * aN.x + b1n[2 * lane + 0], 0.f);
    r.y = fmaxf(cp * aP.y + b1p[2 * lane + 1], 0.f) - fmaxf(cn * aN.y + b1n[2 * lane + 1], 0.f);
    *(float2*)(z + (size_t)node * 64 + lane * 2) = r;

    int k = 2 * lane;
    float s0 = r.x * Wcs[k * 2 + 0] + r.y * Wcs[(k + 1) * 2 + 0];
    float s1 = r.x * Wcs[k * 2 + 1] + r.y * Wcs[(k + 1) * 2 + 1];
    float d0 = r.x * Wcs[128 + k * 2 + 0] + r.y * Wcs[128 + (k + 1) * 2 + 0];
    float d1 = r.x * Wcs[128 + k * 2 + 1] + r.y * Wcs[128 + (k + 1) * 2 + 1];
    #pragma unroll
    for (int o = 16; o > 0; o >>= 1) {
        s0 += __shfl_xor_sync(0xffffffffu, s0, o);
        s1 += __shfl_xor_sync(0xffffffffu, s1, o);
        d0 += __shfl_xor_sync(0xffffffffu, d0, o);
        d1 += __shfl_xor_sync(0xffffffffu, d1, o);
    }
    if (lane == 0) ((float4*)proj)[node] = make_float4(s0, s1, d0, d1);
}

// ---------------- classifier --------------------------------------------------
__global__ void cls_kernel(const float* __restrict__ p, const int* __restrict__ ei,
                           const float* __restrict__ bc, float* __restrict__ out, int nQ) {
    int q = blockIdx.x * blockDim.x + threadIdx.x;
    if (q >= nQ) return;
    int s = __ldg(ei + q);
    int d = __ldg(ei + nQ + q);
    float4 ps = ((const float4*)p)[s];
    float4 pd = ((const float4*)p)[d];
    float l0 = ps.x + pd.z + bc[0];
    float l1 = ps.y + pd.w + bc[1];
    float2 o;
    o.x = 1.f / (1.f + __expf(-l0));
    o.y = 1.f / (1.f + __expf(-l1));
    ((float2*)out)[q] = o;
}

// ---------------- launch -------------------------------------------------------
static inline int cdiv(long long a, int b) { return (int)((a + b - 1) / b); }

extern "C" void kernel_launch(void* const* d_in, const int* in_sizes, int n_in,
                              void* d_out, int out_size) {
    const float* x    = (const float*)d_in[0];
    const float* W0p  = (const float*)d_in[1];
    const float* b0p  = (const float*)d_in[2];
    const float* W0n  = (const float*)d_in[3];
    const float* b0n  = (const float*)d_in[4];
    const float* W1p  = (const float*)d_in[5];
    const float* b1p  = (const float*)d_in[6];
    const float* W1n  = (const float*)d_in[7];
    const float* b1n  = (const float*)d_in[8];
    const float* Wc   = (const float*)d_in[9];
    const float* bc   = (const float*)d_in[10];
    const int*   srcp = (const int*)d_in[11];
    const int*   dstp = (const int*)d_in[12];
    const int*   srcn = (const int*)d_in[13];
    const int*   dstn = (const int*)d_in[14];
    const int*   ei   = (const int*)d_in[15];

    const int n   = in_sizes[0] / HH;
    const int nEp = in_sizes[11];
    const int nEn = in_sizes[13];
    const int nQ  = in_sizes[15] / 2;

    __half *x16, *y, *h;
    float *norms, *pbuf;
    int *cnt, *off, *rank, *csr, *flag, *pval, *ival;
    cudaGetSymbolAddress((void**)&x16,   g_x16);
    cudaGetSymbolAddress((void**)&y,     g_y);
    cudaGetSymbolAddress((void**)&h,     g_h);
    cudaGetSymbolAddress((void**)&norms, g_norms);
    cudaGetSymbolAddress((void**)&cnt,   g_cnt);
    cudaGetSymbolAddress((void**)&off,   g_off);
    cudaGetSymbolAddress((void**)&rank,  g_rank);
    cudaGetSymbolAddress((void**)&csr,   g_csr);
    cudaGetSymbolAddress((void**)&flag,  g_flag);
    cudaGetSymbolAddress((void**)&pval,  g_pval);
    cudaGetSymbolAddress((void**)&ival,  g_ival);
    cudaGetSymbolAddress((void**)&pbuf,  g_proj);

    float* z     = (float*)d_out;
    float* probs = (float*)d_out + (size_t)n * HH;

    const int nb    = cdiv(n, 1024);              // 98 (<=128)
    const int nx4   = n * 16;                     // float4 chunks of x
    const int gGemm = cdiv(n, 128);
    const int gScat = cdiv(nEp > nEn ? nEp : nEn, 256);
    const int gAgg  = cdiv(n, 8);

    // 1) zero counts+flags, convert x -> fp16
    prep_kernel<<<cdiv((long long)n + 256 + nx4, 256), 256>>>(x, (int4*)cnt, flag,
                                                              x16, n, nx4);
    // 2) degrees; dst passes record per-edge rank
    deg4_kernel<<<dim3(cdiv(nEp, 256), 4), 256>>>(srcp, dstp, srcn, dstn, cnt,
                                                  rank, n, nEp);
    // 3) norms + CSR offsets in one launch (decoupled lookback)
    scan_lb_norm<<<dim3(nb, 4), 256>>>(cnt, norms, flag, pval, ival, off,
                                       n, nEp, nEn);
    // 4) layer-1 GEMM (tensor cores, fp16 x) + atomic-free CSR scatter
    gemm1_scatter<<<2 * gGemm + 2 * gScat, 256>>>(
        x16, norms, W0p, W0n, y, srcp, dstp, srcn, dstn, off, rank, csr,
        n, nEp, nEn, gGemm, gScat);
    // 5) layer-1 aggregation (both rels per warp, dual-stream) -> h (fp16)
    agg_l1<<<gAgg, 256>>>(y, off, csr, norms, b0p, b0n, h, n);
    // 6) layer-2 GEMM (fp16 input, tensor cores)
    gemm_l2<<<dim3(gGemm, 2), 256>>>(h, norms, W1p, W1n, y, n);
    // 7) layer-2 aggregation (dual-stream) + combine + classifier projection
    agg_l2<<<gAgg, 256>>>(y, off, csr, norms, b1p, b1n, Wc, z, pbuf, n);
    // 8) classifier
    cls_kernel<<<cdiv(nQ, 256), 256>>>(pbuf, ei, bc, probs, nQ);
}

// round 14
// speedup vs baseline: 1.0655x; 1.0305x over previous
#include <cuda_runtime.h>
#include <cuda_fp16.h>
#include <mma.h>
#include <math.h>

using namespace nvcuda;

#define NN 100000
#define EE 1600000
#define HH 64
#define XS_LD 80   // padded smem stride (halves / floats)

typedef unsigned long long u64;

// ---------------- scratch (device globals) ----------------------------------
__device__ __half g_x16[(size_t)NN * HH];    // x converted to fp16
__device__ __half g_w16[4 * HH * HH];        // W0p|W0n|W1p|W1n in fp16
__device__ __half g_y[2 * (size_t)NN * HH];  // GEMM outputs (fp16)
__device__ __half g_h[2 * (size_t)NN * HH];  // layer-1 activations (fp16)
__device__ float  g_norms[4 * NN];           // csp | cdp | csn | cdn
__device__ int    g_cnt[4 * NN];             // int degree counts (same layout)
__device__ int    g_off[2 * (NN + 1)];       // CSR row offsets (dst) per relation
__device__ int    g_rank[2 * (size_t)EE];    // per-edge rank within dst bucket
__device__ int    g_csr[2 * EE];             // src ids grouped by dst
__device__ int    g_flag[2 * 128];           // lookback flags (0/1/2)
__device__ int    g_pval[2 * 128];           // block partial sums
__device__ int    g_ival[2 * 128];           // block inclusive prefixes
__device__ float  g_proj[4 * NN];            // classifier projections [N][4]

// ---------------- prep: zero cnt+flags, x -> fp16, W -> fp16 -----------------
__global__ void prep_kernel(const float* __restrict__ x,
                            const float* __restrict__ W0p, const float* __restrict__ W0n,
                            const float* __restrict__ W1p, const float* __restrict__ W1n,
                            int4* __restrict__ cnt4, int* __restrict__ flag,
                            __half* __restrict__ x16, __half* __restrict__ w16,
                            int n, int nx4) {
    int t = blockIdx.x * blockDim.x + threadIdx.x;
    if (t < n) { cnt4[t] = make_int4(0, 0, 0, 0); return; }
    if (t < n + 256) { flag[t - n] = 0; return; }
    int c = t - (n + 256);
    if (c < nx4) {
        float4 v = ((const float4*)x)[c];
        __half2 h[2] = {__floats2half2_rn(v.x, v.y), __floats2half2_rn(v.z, v.w)};
        ((uint2*)x16)[c] = *(const uint2*)h;
        return;
    }
    c -= nx4;
    if (c < 4096) {                      // 4 matrices x 4096 floats / 4
        int m = c >> 10, i = c & 1023;
        const float* W = (m == 0) ? W0p : (m == 1) ? W0n : (m == 2) ? W1p : W1n;
        float4 v = ((const float4*)W)[i];
        __half2 h[2] = {__floats2half2_rn(v.x, v.y), __floats2half2_rn(v.z, v.w)};
        ((uint2*)w16)[c] = *(const uint2*)h;
    }
}

// ---------------- degrees; dst passes also record per-edge rank --------------
__global__ void deg4_kernel(const int* __restrict__ sp, const int* __restrict__ dp,
                            const int* __restrict__ sn, const int* __restrict__ dn,
                            int* __restrict__ cnt, int* __restrict__ rank,
                            int n, int nE) {
    int t = blockIdx.x * blockDim.x + threadIdx.x;
    if (t >= nE) return;
    int w = blockIdx.y;
    if (w == 0)      atomicAdd(cnt + sp[t], 1);
    else if (w == 2) atomicAdd(cnt + 2 * (size_t)n + sn[t], 1);
    else if (w == 1) rank[t] = atomicAdd(cnt + (size_t)n + dp[t], 1);
    else             rank[(size_t)EE + t] = atomicAdd(cnt + 3 * (size_t)n + dn[t], 1);
}

// ---------------- one-launch scan: norms (all 4) + CSR offsets (lookback) ----
__global__ void scan_lb_norm(const int* __restrict__ cnt, float* __restrict__ norms,
                             volatile int* flag, volatile int* pval, volatile int* ival,
                             int* __restrict__ offv, int n, int nEp, int nEn) {
    int w = blockIdx.y;                 // 0..3
    int bx = blockIdx.x;
    int tid = threadIdx.x;
    const int* c = cnt + (size_t)w * n;
    float* nm = norms + (size_t)w * n;
    int base = bx * 1024 + tid * 4;

    int v[4], s = 0;
    #pragma unroll
    for (int j = 0; j < 4; j++) {
        int i = base + j;
        v[j] = (i < n) ? c[i] : 0;
        s += v[j];
        if (i < n) nm[i] = (v[j] > 0) ? rsqrtf((float)v[j]) : 0.f;
    }
    if (!(w & 1)) return;               // only dst arrays build CSR
    int rel = w >> 1;
    int sbase = rel * 128;

    __shared__ int sm[256];
    sm[tid] = s; __syncthreads();
    for (int ofs = 1; ofs < 256; ofs <<= 1) {
        int a = (tid >= ofs) ? sm[tid - ofs] : 0;
        __syncthreads();
        sm[tid] += a;
        __syncthreads();
    }
    int excl = sm[tid] - s;
    int bsum = sm[255];

    __shared__ int bprefix;
    if (tid == 0) {
        pval[sbase + bx] = bsum;
        __threadfence();
        flag[sbase + bx] = 1;
        int pref = 0;
        for (int p = bx - 1; p >= 0; ) {
            int f;
            do { f = flag[sbase + p]; } while (f == 0);
            if (f == 2) { pref += ival[sbase + p]; break; }
            pref += pval[sbase + p];
            p--;
        }
        ival[sbase + bx] = pref + bsum;
        __threadfence();
        flag[sbase + bx] = 2;
        bprefix = pref;
    }
    __syncthreads();

    int ex = bprefix + excl;
    int* o = offv + (size_t)rel * (n + 1);
    #pragma unroll
    for (int j = 0; j < 4; j++) {
        int i = base + j;
        if (i < n) o[i] = ex;
        ex += v[j];
    }
    if (bx == 0 && tid == 0) o[n] = rel ? nEn : nEp;
}

// ---------------- wmma GEMM body (fp16 X and W), smem union (40 KB) ----------
__device__ __forceinline__ void gemm_body(const __half* __restrict__ X,
                                          const float* __restrict__ cs,
                                          const __half* __restrict__ W16,
                                          __half* __restrict__ Yo, int n, int blk) {
    __shared__ __align__(16) float sbuf[128 * XS_LD];   // 40960 B
    __half* Wh = (__half*)sbuf;
    __half* Xh = ((__half*)sbuf) + 64 * XS_LD;
    float*  Os = sbuf;                                  // reused after MMA

    int tid = threadIdx.x;
    int row0 = blk * 128;

    for (int i = tid; i < 1024; i += 256) {             // W: raw fp16 copy
        int k = i >> 4, j = i & 15;
        *(uint2*)&Wh[k * XS_LD + 4 * j] = ((const uint2*)W16)[(size_t)k * 16 + j];
    }
    for (int i = tid; i < 2048; i += 256) {
        int r = i >> 4, kq = i & 15;
        int gr = row0 + r;
        uint2 v2 = (gr < n) ? __ldg((const uint2*)X + (size_t)gr * 16 + kq)
                            : make_uint2(0, 0);
        *(uint2*)&Xh[r * XS_LD + 4 * kq] = v2;
    }
    __syncthreads();

    int w = tid >> 5;
    wmma::fragment<wmma::accumulator, 16, 16, 16, float> acc[4];
    #pragma unroll
    for (int t = 0; t < 4; t++) wmma::fill_fragment(acc[t], 0.f);
    #pragma unroll
    for (int k = 0; k < 64; k += 16) {
        wmma::fragment<wmma::matrix_a, 16, 16, 16, __half, wmma::row_major> a;
        wmma::load_matrix_sync(a, &Xh[(w * 16) * XS_LD + k], XS_LD);
        #pragma unroll
        for (int t = 0; t < 4; t++) {
            wmma::fragment<wmma::matrix_b, 16, 16, 16, __half, wmma::row_major> b;
            wmma::load_matrix_sync(b, &Wh[k * XS_LD + t * 16], XS_LD);
            wmma::mma_sync(acc[t], a, b, acc[t]);
        }
    }
    __syncthreads();             // all reads of Wh/Xh done; Os may overwrite
    #pragma unroll
    for (int t = 0; t < 4; t++)
        wmma::store_matrix_sync(&Os[(w * 16) * XS_LD + t * 16], acc[t], XS_LD,
                                wmma::mem_row_major);
    __syncthreads();

    for (int i = tid; i < 2048; i += 256) {
        int r = i >> 4, q = i & 15;
        int gr = row0 + r;
        if (gr >= n) continue;
        float c = cs[gr];
        float4 v = *(const float4*)&Os[r * XS_LD + 4 * q];
        __half2 o[2] = {__floats2half2_rn(v.x * c, v.y * c),
                        __floats2half2_rn(v.z * c, v.w * c)};
        *(uint2*)(Yo + (size_t)gr * 64 + 4 * q) = *(const uint2*)o;
    }
}

// ---------------- fat kernel: layer-1 GEMM (both rels) + vectorized scatter --
__global__ void __launch_bounds__(256, 4)
gemm1_scatter(const __half* __restrict__ x16, const __half* __restrict__ w16,
              const float* __restrict__ norms, __half* __restrict__ Y,
              const int* __restrict__ srcp, const int* __restrict__ dstp,
              const int* __restrict__ srcn, const int* __restrict__ dstn,
              const int* __restrict__ off, const int* __restrict__ rank,
              int* __restrict__ csr,
              int n, int nEp, int nEn, int gGemm, int gScat) {
    int b = blockIdx.x;
    if (b < 2 * gGemm) {
        int rel = b / gGemm;
        gemm_body(x16, norms + 2 * (size_t)rel * n, w16 + (size_t)rel * 4096,
                  Y + (size_t)rel * n * 64, n, b % gGemm);
    } else {
        int sb = b - 2 * gGemm;
        int rel = sb / gScat;
        int e4 = ((sb % gScat) * 256 + threadIdx.x) * 4;   // 4 edges per thread
        int nE = rel ? nEn : nEp;
        if (e4 >= nE) return;
        const int* src = rel ? srcn : srcp;
        const int* dst = rel ? dstn : dstp;
        const int* ofr = off + (size_t)rel * (n + 1);
        const int* rk  = rank + (size_t)rel * EE;
        int* cs_ = csr + (size_t)rel * EE;
        if (e4 + 4 <= nE) {
            int4 d4 = *(const int4*)(dst + e4);
            int4 r4 = *(const int4*)(rk + e4);
            int4 s4 = *(const int4*)(src + e4);
            cs_[__ldg(ofr + d4.x) + r4.x] = s4.x;
            cs_[__ldg(ofr + d4.y) + r4.y] = s4.y;
            cs_[__ldg(ofr + d4.z) + r4.z] = s4.z;
            cs_[__ldg(ofr + d4.w) + r4.w] = s4.w;
        } else {
            for (int e = e4; e < nE; e++)
                cs_[__ldg(ofr + dst[e]) + rk[e]] = src[e];
        }
    }
}

// ---------------- layer-2 GEMM (fp16 input) ----------------------------------
__global__ void __launch_bounds__(256, 4)
gemm_l2(const __half* __restrict__ h, const __half* __restrict__ w16,
        const float* __restrict__ norms, __half* __restrict__ Y, int n) {
    int rel = blockIdx.y;
    gemm_body(h + (size_t)rel * n * 64, norms + 2 * (size_t)rel * n,
              w16 + (2 + (size_t)rel) * 4096, Y + (size_t)rel * n * 64, n, blockIdx.x);
}

// ---------------- dual-stream CSR pull: two independent idx->payload chains --
__device__ __forceinline__ void csr_sum_dual(
    const int* __restrict__ off0, const int* __restrict__ csr0,
    const __half2* __restrict__ yl0,
    const int* __restrict__ off1, const int* __restrict__ csr1,
    const __half2* __restrict__ yl1,
    int node, float2& r0, float2& r1) {
    int j0 = __ldg(off0 + node), e0 = __ldg(off0 + node + 1);
    int j1 = __ldg(off1 + node), e1 = __ldg(off1 + node + 1);
    float2 a00 = make_float2(0.f, 0.f), a01 = make_float2(0.f, 0.f);
    float2 a10 = make_float2(0.f, 0.f), a11 = make_float2(0.f, 0.f);

    while (j0 + 2 <= e0 && j1 + 2 <= e1) {
        int sA = __ldg(csr0 + j0);
        int sB = __ldg(csr0 + j0 + 1);
        int sC = __ldg(csr1 + j1);
        int sD = __ldg(csr1 + j1 + 1);
        __half2 hA = __ldg(yl0 + (size_t)sA * 32);
        __half2 hB = __ldg(yl0 + (size_t)sB * 32);
        __half2 hC = __ldg(yl1 + (size_t)sC * 32);
        __half2 hD = __ldg(yl1 + (size_t)sD * 32);
        float2 vA = __half22float2(hA); a00.x += vA.x; a00.y += vA.y;
        float2 vB = __half22float2(hB); a01.x += vB.x; a01.y += vB.y;
        float2 vC = __half22float2(hC); a10.x += vC.x; a10.y += vC.y;
        float2 vD = __half22float2(hD); a11.x += vD.x; a11.y += vD.y;
        j0 += 2; j1 += 2;
    }
    for (; j0 + 2 <= e0; j0 += 2) {
        int sA = __ldg(csr0 + j0);
        int sB = __ldg(csr0 + j0 + 1);
        __half2 hA = __ldg(yl0 + (size_t)sA * 32);
        __half2 hB = __ldg(yl0 + (size_t)sB * 32);
        float2 vA = __half22float2(hA); a00.x += vA.x; a00.y += vA.y;
        float2 vB = __half22float2(hB); a01.x += vB.x; a01.y += vB.y;
    }
    if (j0 < e0) {
        int sA = __ldg(csr0 + j0);
        float2 vA = __half22float2(__ldg(yl0 + (size_t)sA * 32));
        a00.x += vA.x; a00.y += vA.y;
    }
    for (; j1 + 2 <= e1; j1 += 2) {
        int sC = __ldg(csr1 + j1);
        int sD = __ldg(csr1 + j1 + 1);
        __half2 hC = __ldg(yl1 + (size_t)sC * 32);
        __half2 hD = __ldg(yl1 + (size_t)sD * 32);
        float2 vC = __half22float2(hC); a10.x += vC.x; a10.y += vC.y;
        float2 vD = __half22float2(hD); a11.x += vD.x; a11.y += vD.y;
    }
    if (j1 < e1) {
        int sC = __ldg(csr1 + j1);
        float2 vC = __half22float2(__ldg(yl1 + (size_t)sC * 32));
        a10.x += vC.x; a10.y += vC.y;
    }
    r0 = make_float2(a00.x + a01.x, a00.y + a01.y);
    r1 = make_float2(a10.x + a11.x, a10.y + a11.y);
}

// layer 1, both relations per warp: h_rel[i,:] = half(relu(c_dst * sum + b0))
__global__ void agg_l1(const __half* __restrict__ y, const int* __restrict__ off,
                       const int* __restrict__ csr, const float* __restrict__ norms,
                       const float* __restrict__ b0p, const float* __restrict__ b0n,
                       __half* __restrict__ h, int n) {
    int node = blockIdx.x * 8 + (threadIdx.x >> 5);
    if (node >= n) return;
    int lane = threadIdx.x & 31;
    const __half2* yl0 = (const __half2*)y + lane;
    const __half2* yl1 = (const __half2*)(y + (size_t)n * 64) + lane;
    float2 aP, aN;
    csr_sum_dual(off, csr, yl0, off + (n + 1), csr + (size_t)EE, yl1, node, aP, aN);
    float c0 = norms[(size_t)n + node];
    float c1 = norms[3 * (size_t)n + node];
    float2 bp = *(const float2*)(b0p + 2 * lane);
    float2 bn = *(const float2*)(b0n + 2 * lane);
    ((__half2*)(h + (size_t)node * 64))[lane] =
        __floats2half2_rn(fmaxf(c0 * aP.x + bp.x, 0.f), fmaxf(c0 * aP.y + bp.y, 0.f));
    ((__half2*)(h + ((size_t)n + node) * 64))[lane] =
        __floats2half2_rn(fmaxf(c1 * aN.x + bn.x, 0.f), fmaxf(c1 * aN.y + bn.y, 0.f));
}

// layer 2: z = relu(cdp*sumP + b1p) - relu(cdn*sumN + b1n) + fused projection
__global__ void agg_l2(const __half* __restrict__ y, const int* __restrict__ off,
                       const int* __restrict__ csr, const float* __restrict__ norms,
                       const float* __restrict__ b1p, const float* __restrict__ b1n,
                       const float* __restrict__ Wc,
                       float* __restrict__ z, float* __restrict__ proj, int n) {
    __shared__ float Wcs[256];
    Wcs[threadIdx.x] = Wc[threadIdx.x];   // blockDim == 256
    __syncthreads();

    int node = blockIdx.x * 8 + (threadIdx.x >> 5);
    if (node >= n) return;
    int lane = threadIdx.x & 31;
    const __half2* yl0 = (const __half2*)y + lane;
    const __half2* yl1 = (const __half2*)(y + (size_t)n * 64) + lane;
    float2 aP, aN;
    csr_sum_dual(off, csr, yl0, off + (n + 1), csr + (size_t)EE, yl1, node, aP, aN);
    float cp = norms[(size_t)n + node];
    float cn = norms[3 * (size_t)n + node];
    float2 r;
    r.x = fmaxf(cp * aP.x + b1p[2 * lane + 0], 0.f) - fmaxf(cn * aN.x + b1n[2 * lane + 0], 0.f);
    r.y = fmaxf(cp * aP.y + b1p[2 * lane + 1], 0.f) - fmaxf(cn * aN.y + b1n[2 * lane + 1], 0.f);
    *(float2*)(z + (size_t)node * 64 + lane * 2) = r;

    int k = 2 * lane;
    float s0 = r.x * Wcs[k * 2 + 0] + r.y * Wcs[(k + 1) * 2 + 0];
    float s1 = r.x * Wcs[k * 2 + 1] + r.y * Wcs[(k + 1) * 2 + 1];
    float d0 = r.x * Wcs[128 + k * 2 + 0] + r.y * Wcs[128 + (k + 1) * 2 + 0];
    float d1 = r.x * Wcs[128 + k * 2 + 1] + r.y * Wcs[128 + (k + 1) * 2 + 1];
    #pragma unroll
    for (int o = 16; o > 0; o >>= 1) {
        s0 += __shfl_xor_sync(0xffffffffu, s0, o);
        s1 += __shfl_xor_sync(0xffffffffu, s1, o);
        d0 += __shfl_xor_sync(0xffffffffu, d0, o);
        d1 += __shfl_xor_sync(0xffffffffu, d1, o);
    }
    if (lane == 0) ((float4*)proj)[node] = make_float4(s0, s1, d0, d1);
}

// ---------------- classifier --------------------------------------------------
__global__ void cls_kernel(const float* __restrict__ p, const int* __restrict__ ei,
                           const float* __restrict__ bc, float* __restrict__ out, int nQ) {
    int q = blockIdx.x * blockDim.x + threadIdx.x;
    if (q >= nQ) return;
    int s = __ldg(ei + q);
    int d = __ldg(ei + nQ + q);
    float4 ps = ((const float4*)p)[s];
    float4 pd = ((const float4*)p)[d];
    float l0 = ps.x + pd.z + bc[0];
    float l1 = ps.y + pd.w + bc[1];
    float2 o;
    o.x = 1.f / (1.f + __expf(-l0));
    o.y = 1.f / (1.f + __expf(-l1));
    ((float2*)out)[q] = o;
}

// ---------------- launch -------------------------------------------------------
static inline int cdiv(long long a, int b) { return (int)((a + b - 1) / b); }

extern "C" void kernel_launch(void* const* d_in, const int* in_sizes, int n_in,
                              void* d_out, int out_size) {
    const float* x    = (const float*)d_in[0];
    const float* W0p  = (const float*)d_in[1];
    const float* b0p  = (const float*)d_in[2];
    const float* W0n  = (const float*)d_in[3];
    const float* b0n  = (const float*)d_in[4];
    const float* W1p  = (const float*)d_in[5];
    const float* b1p  = (const float*)d_in[6];
    const float* W1n  = (const float*)d_in[7];
    const float* b1n  = (const float*)d_in[8];
    const float* Wc   = (const float*)d_in[9];
    const float* bc   = (const float*)d_in[10];
    const int*   srcp = (const int*)d_in[11];
    const int*   dstp = (const int*)d_in[12];
    const int*   srcn = (const int*)d_in[13];
    const int*   dstn = (const int*)d_in[14];
    const int*   ei   = (const int*)d_in[15];

    const int n   = in_sizes[0] / HH;
    const int nEp = in_sizes[11];
    const int nEn = in_sizes[13];
    const int nQ  = in_sizes[15] / 2;

    __half *x16, *w16, *y, *h;
    float *norms, *pbuf;
    int *cnt, *off, *rank, *csr, *flag, *pval, *ival;
    cudaGetSymbolAddress((void**)&x16,   g_x16);
    cudaGetSymbolAddress((void**)&w16,   g_w16);
    cudaGetSymbolAddress((void**)&y,     g_y);
    cudaGetSymbolAddress((void**)&h,     g_h);
    cudaGetSymbolAddress((void**)&norms, g_norms);
    cudaGetSymbolAddress((void**)&cnt,   g_cnt);
    cudaGetSymbolAddress((void**)&off,   g_off);
    cudaGetSymbolAddress((void**)&rank,  g_rank);
    cudaGetSymbolAddress((void**)&csr,   g_csr);
    cudaGetSymbolAddress((void**)&flag,  g_flag);
    cudaGetSymbolAddress((void**)&pval,  g_pval);
    cudaGetSymbolAddress((void**)&ival,  g_ival);
    cudaGetSymbolAddress((void**)&pbuf,  g_proj);

    float* z     = (float*)d_out;
    float* probs = (float*)d_out + (size_t)n * HH;

    const int nb    = cdiv(n, 1024);              // 98 (<=128)
    const int nx4   = n * 16;                     // float4 chunks of x
    const int gGemm = cdiv(n, 128);
    const int gScat = cdiv(nEp > nEn ? nEp : nEn, 1024);   // 4 edges/thread
    const int gAgg  = cdiv(n, 8);

    // 1) zero counts+flags, x -> fp16, W -> fp16
    prep_kernel<<<cdiv((long long)n + 256 + nx4 + 4096, 256), 256>>>(
        x, W0p, W0n, W1p, W1n, (int4*)cnt, flag, x16, w16, n, nx4);
    // 2) degrees; dst passes record per-edge rank
    deg4_kernel<<<dim3(cdiv(nEp, 256), 4), 256>>>(srcp, dstp, srcn, dstn, cnt,
                                                  rank, n, nEp);
    // 3) norms + CSR offsets in one launch (decoupled lookback)
    scan_lb_norm<<<dim3(nb, 4), 256>>>(cnt, norms, flag, pval, ival, off,
                                       n, nEp, nEn);
    // 4) layer-1 GEMM (tensor cores, fp16 W+X) + vectorized atomic-free scatter
    gemm1_scatter<<<2 * gGemm + 2 * gScat, 256>>>(
        x16, w16, norms, y, srcp, dstp, srcn, dstn, off, rank, csr,
        n, nEp, nEn, gGemm, gScat);
    // 5) layer-1 aggregation (both rels per warp, dual-stream) -> h (fp16)
    agg_l1<<<gAgg, 256>>>(y, off, csr, norms, b0p, b0n, h, n);
    // 6) layer-2 GEMM (fp16 input, tensor cores)
    gemm_l2<<<dim3(gGemm, 2), 256>>>(h, w16, norms, y, n);
    // 7) layer-2 aggregation (dual-stream) + combine + classifier projection
    agg_l2<<<gAgg, 256>>>(y, off, csr, norms, b1p, b1n, Wc, z, pbuf, n);
    // 8) classifier
    cls_kernel<<<cdiv(nQ, 256), 256>>>(pbuf, ei, bc, probs, nQ);
}

// round 15
// speedup vs baseline: 1.0795x; 1.0131x over previous
#include <cuda_runtime.h>
#include <cuda_fp16.h>
#include <mma.h>
#include <math.h>

using namespace nvcuda;

#define NN 100000
#define EE 1600000
#define HH 64
#define XS_LD 80   // padded smem stride (halves / floats)

typedef unsigned long long u64;

// ---------------- scratch (device globals) ----------------------------------
__device__ __half g_x16[(size_t)NN * HH];    // x converted to fp16
__device__ __half g_w16[4 * HH * HH];        // W0p|W0n|W1p|W1n in fp16
__device__ __half g_y[2 * (size_t)NN * HH];  // GEMM outputs (fp16)
__device__ __half g_h[2 * (size_t)NN * HH];  // layer-1 activations (fp16)
__device__ float  g_norms[4 * NN];           // csp | cdp | csn | cdn
__device__ int    g_cnt[4 * NN];             // int degree counts (same layout)
__device__ int    g_off[2 * (NN + 1)];       // CSR row offsets (dst) per relation
__device__ int    g_rank[2 * (size_t)EE];    // per-edge rank within dst bucket
__device__ int    g_csr[2 * EE];             // src ids grouped by dst
__device__ int    g_flag[2 * 128];           // lookback flags (0/1/2)
__device__ int    g_pval[2 * 128];           // block partial sums
__device__ int    g_ival[2 * 128];           // block inclusive prefixes
__device__ float  g_proj[4 * NN];            // classifier projections [N][4]

// ---------------- zero: counts + lookback flags (tiny, fast) -----------------
__global__ void zero_kernel(int4* __restrict__ cnt4, int* __restrict__ flag, int n) {
    int t = blockIdx.x * blockDim.x + threadIdx.x;
    if (t < n) cnt4[t] = make_int4(0, 0, 0, 0);
    else if (t < n + 256) flag[t - n] = 0;
}

// ---------------- fat kernel: degrees/ranks (4 edges/thread) + fp16 convs ----
__device__ __forceinline__ void deg_seg(const int* __restrict__ idx,
                                        int* __restrict__ cnt, int nE, int blk) {
    int e4 = (blk * 256 + threadIdx.x) * 4;
    if (e4 + 4 <= nE) {
        int4 v = *(const int4*)(idx + e4);
        atomicAdd(cnt + v.x, 1); atomicAdd(cnt + v.y, 1);
        atomicAdd(cnt + v.z, 1); atomicAdd(cnt + v.w, 1);
    } else {
        for (int e = e4; e < nE; e++) atomicAdd(cnt + idx[e], 1);
    }
}

__device__ __forceinline__ void rank_seg(const int* __restrict__ idx,
                                         int* __restrict__ cnt, int* __restrict__ rank,
                                         int nE, int blk) {
    int e4 = (blk * 256 + threadIdx.x) * 4;
    if (e4 + 4 <= nE) {
        int4 v = *(const int4*)(idx + e4);
        int4 r;
        r.x = atomicAdd(cnt + v.x, 1);
        r.y = atomicAdd(cnt + v.y, 1);
        r.z = atomicAdd(cnt + v.z, 1);
        r.w = atomicAdd(cnt + v.w, 1);
        *(int4*)(rank + e4) = r;
    } else {
        for (int e = e4; e < nE; e++) rank[e] = atomicAdd(cnt + idx[e], 1);
    }
}

__global__ void deg_conv(const int* __restrict__ sp, const int* __restrict__ dp,
                         const int* __restrict__ sn, const int* __restrict__ dn,
                         int* __restrict__ cnt, int* __restrict__ rank,
                         const float* __restrict__ x, __half* __restrict__ x16,
                         const float* __restrict__ W0p, const float* __restrict__ W0n,
                         const float* __restrict__ W1p, const float* __restrict__ W1n,
                         __half* __restrict__ w16,
                         int n, int nEp, int nEn, int gEp, int gEn, int gX, int nx4) {
    int b = blockIdx.x;
    if (b < gEp) { deg_seg(sp, cnt, nEp, b); return; }
    b -= gEp;
    if (b < gEp) { rank_seg(dp, cnt + (size_t)n, rank, nEp, b); return; }
    b -= gEp;
    if (b < gEn) { deg_seg(sn, cnt + 2 * (size_t)n, nEn, b); return; }
    b -= gEn;
    if (b < gEn) { rank_seg(dn, cnt + 3 * (size_t)n, rank + (size_t)EE, nEn, b); return; }
    b -= gEn;
    if (b < gX) {                        // x fp32 -> fp16, 4 float4 chunks/thread
        int c0 = (b * 256 + threadIdx.x) * 4;
        #pragma unroll
        for (int j = 0; j < 4; j++) {
            int c = c0 + j;
            if (c < nx4) {
                float4 v = ((const float4*)x)[c];
                __half2 h[2] = {__floats2half2_rn(v.x, v.y),
                                __floats2half2_rn(v.z, v.w)};
                ((uint2*)x16)[c] = *(const uint2*)h;
            }
        }
        return;
    }
    b -= gX;
    {                                    // W fp32 -> fp16 (16 blocks)
        int c = b * 256 + threadIdx.x;   // 4096 float4 chunks total
        if (c < 4096) {
            int m = c >> 10, i = c & 1023;
            const float* W = (m == 0) ? W0p : (m == 1) ? W0n : (m == 2) ? W1p : W1n;
            float4 v = ((const float4*)W)[i];
            __half2 h[2] = {__floats2half2_rn(v.x, v.y), __floats2half2_rn(v.z, v.w)};
            ((uint2*)w16)[c] = *(const uint2*)h;
        }
    }
}

// ---------------- one-launch scan: norms (all 4) + CSR offsets (lookback) ----
__global__ void scan_lb_norm(const int* __restrict__ cnt, float* __restrict__ norms,
                             volatile int* flag, volatile int* pval, volatile int* ival,
                             int* __restrict__ offv, int n, int nEp, int nEn) {
    int w = blockIdx.y;                 // 0..3
    int bx = blockIdx.x;
    int tid = threadIdx.x;
    const int* c = cnt + (size_t)w * n;
    float* nm = norms + (size_t)w * n;
    int base = bx * 1024 + tid * 4;

    int v[4], s = 0;
    #pragma unroll
    for (int j = 0; j < 4; j++) {
        int i = base + j;
        v[j] = (i < n) ? c[i] : 0;
        s += v[j];
        if (i < n) nm[i] = (v[j] > 0) ? rsqrtf((float)v[j]) : 0.f;
    }
    if (!(w & 1)) return;               // only dst arrays build CSR
    int rel = w >> 1;
    int sbase = rel * 128;

    __shared__ int sm[256];
    sm[tid] = s; __syncthreads();
    for (int ofs = 1; ofs < 256; ofs <<= 1) {
        int a = (tid >= ofs) ? sm[tid - ofs] : 0;
        __syncthreads();
        sm[tid] += a;
        __syncthreads();
    }
    int excl = sm[tid] - s;
    int bsum = sm[255];

    __shared__ int bprefix;
    if (tid == 0) {
        pval[sbase + bx] = bsum;
        __threadfence();
        flag[sbase + bx] = 1;
        int pref = 0;
        for (int p = bx - 1; p >= 0; ) {
            int f;
            do { f = flag[sbase + p]; } while (f == 0);
            if (f == 2) { pref += ival[sbase + p]; break; }
            pref += pval[sbase + p];
            p--;
        }
        ival[sbase + bx] = pref + bsum;
        __threadfence();
        flag[sbase + bx] = 2;
        bprefix = pref;
    }
    __syncthreads();

    int ex = bprefix + excl;
    int* o = offv + (size_t)rel * (n + 1);
    #pragma unroll
    for (int j = 0; j < 4; j++) {
        int i = base + j;
        if (i < n) o[i] = ex;
        ex += v[j];
    }
    if (bx == 0 && tid == 0) o[n] = rel ? nEn : nEp;
}

// ---------------- wmma GEMM body (fp16 X and W), smem union (40 KB) ----------
__device__ __forceinline__ void gemm_body(const __half* __restrict__ X,
                                          const float* __restrict__ cs,
                                          const __half* __restrict__ W16,
                                          __half* __restrict__ Yo, int n, int blk) {
    __shared__ __align__(16) float sbuf[128 * XS_LD];   // 40960 B
    __half* Wh = (__half*)sbuf;
    __half* Xh = ((__half*)sbuf) + 64 * XS_LD;
    float*  Os = sbuf;                                  // reused after MMA

    int tid = threadIdx.x;
    int row0 = blk * 128;

    for (int i = tid; i < 1024; i += 256) {             // W: raw fp16 copy
        int k = i >> 4, j = i & 15;
        *(uint2*)&Wh[k * XS_LD + 4 * j] = ((const uint2*)W16)[(size_t)k * 16 + j];
    }
    for (int i = tid; i < 2048; i += 256) {
        int r = i >> 4, kq = i & 15;
        int gr = row0 + r;
        uint2 v2 = (gr < n) ? __ldg((const uint2*)X + (size_t)gr * 16 + kq)
                            : make_uint2(0, 0);
        *(uint2*)&Xh[r * XS_LD + 4 * kq] = v2;
    }
    __syncthreads();

    int w = tid >> 5;
    wmma::fragment<wmma::accumulator, 16, 16, 16, float> acc[4];
    #pragma unroll
    for (int t = 0; t < 4; t++) wmma::fill_fragment(acc[t], 0.f);
    #pragma unroll
    for (int k = 0; k < 64; k += 16) {
        wmma::fragment<wmma::matrix_a, 16, 16, 16, __half, wmma::row_major> a;
        wmma::load_matrix_sync(a, &Xh[(w * 16) * XS_LD + k], XS_LD);
        #pragma unroll
        for (int t = 0; t < 4; t++) {
            wmma::fragment<wmma::matrix_b, 16, 16, 16, __half, wmma::row_major> b;
            wmma::load_matrix_sync(b, &Wh[k * XS_LD + t * 16], XS_LD);
            wmma::mma_sync(acc[t], a, b, acc[t]);
        }
    }
    __syncthreads();             // all reads of Wh/Xh done; Os may overwrite
    #pragma unroll
    for (int t = 0; t < 4; t++)
        wmma::store_matrix_sync(&Os[(w * 16) * XS_LD + t * 16], acc[t], XS_LD,
                                wmma::mem_row_major);
    __syncthreads();

    for (int i = tid; i < 2048; i += 256) {
        int r = i >> 4, q = i & 15;
        int gr = row0 + r;
        if (gr >= n) continue;
        float c = cs[gr];
        float4 v = *(const float4*)&Os[r * XS_LD + 4 * q];
        __half2 o[2] = {__floats2half2_rn(v.x * c, v.y * c),
                        __floats2half2_rn(v.z * c, v.w * c)};
        *(uint2*)(Yo + (size_t)gr * 64 + 4 * q) = *(const uint2*)o;
    }
}

// ---------------- fat kernel: layer-1 GEMM (both rels) + vectorized scatter --
__global__ void __launch_bounds__(256, 4)
gemm1_scatter(const __half* __restrict__ x16, const __half* __restrict__ w16,
              const float* __restrict__ norms, __half* __restrict__ Y,
              const int* __restrict__ srcp, const int* __restrict__ dstp,
              const int* __restrict__ srcn, const int* __restrict__ dstn,
              const int* __restrict__ off, const int* __restrict__ rank,
              int* __restrict__ csr,
              int n, int nEp, int nEn, int gGemm, int gScat) {
    int b = blockIdx.x;
    if (b < 2 * gGemm) {
        int rel = b / gGemm;
        gemm_body(x16, norms + 2 * (size_t)rel * n, w16 + (size_t)rel * 4096,
                  Y + (size_t)rel * n * 64, n, b % gGemm);
    } else {
        int sb = b - 2 * gGemm;
        int rel = sb / gScat;
        int e4 = ((sb % gScat) * 256 + threadIdx.x) * 4;   // 4 edges per thread
        int nE = rel ? nEn : nEp;
        if (e4 >= nE) return;
        const int* src = rel ? srcn : srcp;
        const int* dst = rel ? dstn : dstp;
        const int* ofr = off + (size_t)rel * (n + 1);
        const int* rk  = rank + (size_t)rel * EE;
        int* cs_ = csr + (size_t)rel * EE;
        if (e4 + 4 <= nE) {
            int4 d4 = *(const int4*)(dst + e4);
            int4 r4 = *(const int4*)(rk + e4);
            int4 s4 = *(const int4*)(src + e4);
            cs_[__ldg(ofr + d4.x) + r4.x] = s4.x;
            cs_[__ldg(ofr + d4.y) + r4.y] = s4.y;
            cs_[__ldg(ofr + d4.z) + r4.z] = s4.z;
            cs_[__ldg(ofr + d4.w) + r4.w] = s4.w;
        } else {
            for (int e = e4; e < nE; e++)
                cs_[__ldg(ofr + dst[e]) + rk[e]] = src[e];
        }
    }
}

// ---------------- layer-2 GEMM (fp16 input) ----------------------------------
__global__ void __launch_bounds__(256, 4)
gemm_l2(const __half* __restrict__ h, const __half* __restrict__ w16,
        const float* __restrict__ norms, __half* __restrict__ Y, int n) {
    int rel = blockIdx.y;
    gemm_body(h + (size_t)rel * n * 64, norms + 2 * (size_t)rel * n,
              w16 + (2 + (size_t)rel) * 4096, Y + (size_t)rel * n * 64, n, blockIdx.x);
}

// ---------------- dual-stream CSR pull: two independent idx->payload chains --
__device__ __forceinline__ void csr_sum_dual(
    const int* __restrict__ off0, const int* __restrict__ csr0,
    const __half2* __restrict__ yl0,
    const int* __restrict__ off1, const int* __restrict__ csr1,
    const __half2* __restrict__ yl1,
    int node, float2& r0, float2& r1) {
    int j0 = __ldg(off0 + node), e0 = __ldg(off0 + node + 1);
    int j1 = __ldg(off1 + node), e1 = __ldg(off1 + node + 1);
    float2 a00 = make_float2(0.f, 0.f), a01 = make_float2(0.f, 0.f);
    float2 a10 = make_float2(0.f, 0.f), a11 = make_float2(0.f, 0.f);

    while (j0 + 2 <= e0 && j1 + 2 <= e1) {
        int sA = __ldg(csr0 + j0);
        int sB = __ldg(csr0 + j0 + 1);
        int sC = __ldg(csr1 + j1);
        int sD = __ldg(csr1 + j1 + 1);
        __half2 hA = __ldg(yl0 + (size_t)sA * 32);
        __half2 hB = __ldg(yl0 + (size_t)sB * 32);
        __half2 hC = __ldg(yl1 + (size_t)sC * 32);
        __half2 hD = __ldg(yl1 + (size_t)sD * 32);
        float2 vA = __half22float2(hA); a00.x += vA.x; a00.y += vA.y;
        float2 vB = __half22float2(hB); a01.x += vB.x; a01.y += vB.y;
        float2 vC = __half22float2(hC); a10.x += vC.x; a10.y += vC.y;
        float2 vD = __half22float2(hD); a11.x += vD.x; a11.y += vD.y;
        j0 += 2; j1 += 2;
    }
    for (; j0 + 2 <= e0; j0 += 2) {
        int sA = __ldg(csr0 + j0);
        int sB = __ldg(csr0 + j0 + 1);
        __half2 hA = __ldg(yl0 + (size_t)sA * 32);
        __half2 hB = __ldg(yl0 + (size_t)sB * 32);
        float2 vA = __half22float2(hA); a00.x += vA.x; a00.y += vA.y;
        float2 vB = __half22float2(hB); a01.x += vB.x; a01.y += vB.y;
    }
    if (j0 < e0) {
        int sA = __ldg(csr0 + j0);
        float2 vA = __half22float2(__ldg(yl0 + (size_t)sA * 32));
        a00.x += vA.x; a00.y += vA.y;
    }
    for (; j1 + 2 <= e1; j1 += 2) {
        int sC = __ldg(csr1 + j1);
        int sD = __ldg(csr1 + j1 + 1);
        __half2 hC = __ldg(yl1 + (size_t)sC * 32);
        __half2 hD = __ldg(yl1 + (size_t)sD * 32);
        float2 vC = __half22float2(hC); a10.x += vC.x; a10.y += vC.y;
        float2 vD = __half22float2(hD); a11.x += vD.x; a11.y += vD.y;
    }
    if (j1 < e1) {
        int sC = __ldg(csr1 + j1);
        float2 vC = __half22float2(__ldg(yl1 + (size_t)sC * 32));
        a10.x += vC.x; a10.y += vC.y;
    }
    r0 = make_float2(a00.x + a01.x, a00.y + a01.y);
    r1 = make_float2(a10.x + a11.x, a10.y + a11.y);
}

// layer 1, both relations per warp: h_rel[i,:] = half(relu(c_dst * sum + b0))
__global__ void agg_l1(const __half* __restrict__ y, const int* __restrict__ off,
                       const int* __restrict__ csr, const float* __restrict__ norms,
                       const float* __restrict__ b0p, const float* __restrict__ b0n,
                       __half* __restrict__ h, int n) {
    int node = blockIdx.x * 8 + (threadIdx.x >> 5);
    if (node >= n) return;
    int lane = threadIdx.x & 31;
    const __half2* yl0 = (const __half2*)y + lane;
    const __half2* yl1 = (const __half2*)(y + (size_t)n * 64) + lane;
    float2 aP, aN;
    csr_sum_dual(off, csr, yl0, off + (n + 1), csr + (size_t)EE, yl1, node, aP, aN);
    float c0 = norms[(size_t)n + node];
    float c1 = norms[3 * (size_t)n + node];
    float2 bp = *(const float2*)(b0p + 2 * lane);
    float2 bn = *(const float2*)(b0n + 2 * lane);
    ((__half2*)(h + (size_t)node * 64))[lane] =
        __floats2half2_rn(fmaxf(c0 * aP.x + bp.x, 0.f), fmaxf(c0 * aP.y + bp.y, 0.f));
    ((__half2*)(h + ((size_t)n + node) * 64))[lane] =
        __floats2half2_rn(fmaxf(c1 * aN.x + bn.x, 0.f), fmaxf(c1 * aN.y + bn.y, 0.f));
}

// layer 2: z = relu(cdp*sumP + b1p) - relu(cdn*sumN + b1n) + fused projection
__global__ void agg_l2(const __half* __restrict__ y, const int* __restrict__ off,
                       const int* __restrict__ csr, const float* __restrict__ norms,
                       const float* __restrict__ b1p, const float* __restrict__ b1n,
                       const float* __restrict__ Wc,
                       float* __restrict__ z, float* __restrict__ proj, int n) {
    __shared__ float Wcs[256];
    Wcs[threadIdx.x] = Wc[threadIdx.x];   // blockDim == 256
    __syncthreads();

    int node = blockIdx.x * 8 + (threadIdx.x >> 5);
    if (node >= n) return;
    int lane = threadIdx.x & 31;
    const __half2* yl0 = (const __half2*)y + lane;
    const __half2* yl1 = (const __half2*)(y + (size_t)n * 64) + lane;
    float2 aP, aN;
    csr_sum_dual(off, csr, yl0, off + (n + 1), csr + (size_t)EE, yl1, node, aP, aN);
    float cp = norms[(size_t)n + node];
    float cn = norms[3 * (size_t)n + node];
    float2 r;
    r.x = fmaxf(cp * aP.x + b1p[2 * lane + 0], 0.f) - fmaxf(cn * aN.x + b1n[2 * lane + 0], 0.f);
    r.y = fmaxf(cp * aP.y + b1p[2 * lane + 1], 0.f) - fmaxf(cn * aN.y + b1n[2 * lane + 1], 0.f);
    *(float2*)(z + (size_t)node * 64 + lane * 2) = r;

    int k = 2 * lane;
    float s0 = r.x * Wcs[k * 2 + 0] + r.y * Wcs[(k + 1) * 2 + 0];
    float s1 = r.x * Wcs[k * 2 + 1] + r.y * Wcs[(k + 1) * 2 + 1];
    float d0 = r.x * Wcs[128 + k * 2 + 0] + r.y * Wcs[128 + (k + 1) * 2 + 0];
    float d1 = r.x * Wcs[128 + k * 2 + 1] + r.y * Wcs[128 + (k + 1) * 2 + 1];
    #pragma unroll
    for (int o = 16; o > 0; o >>= 1) {
        s0 += __shfl_xor_sync(0xffffffffu, s0, o);
        s1 += __shfl_xor_sync(0xffffffffu, s1, o);
        d0 += __shfl_xor_sync(0xffffffffu, d0, o);
        d1 += __shfl_xor_sync(0xffffffffu, d1, o);
    }
    if (lane == 0) ((float4*)proj)[node] = make_float4(s0, s1, d0, d1);
}

// ---------------- classifier --------------------------------------------------
__global__ void cls_kernel(const float* __restrict__ p, const int* __restrict__ ei,
                           const float* __restrict__ bc, float* __restrict__ out, int nQ) {
    int q = blockIdx.x * blockDim.x + threadIdx.x;
    if (q >= nQ) return;
    int s = __ldg(ei + q);
    int d = __ldg(ei + nQ + q);
    float4 ps = ((const float4*)p)[s];
    float4 pd = ((const float4*)p)[d];
    float l0 = ps.x + pd.z + bc[0];
    float l1 = ps.y + pd.w + bc[1];
    float2 o;
    o.x = 1.f / (1.f + __expf(-l0));
    o.y = 1.f / (1.f + __expf(-l1));
    ((float2*)out)[q] = o;
}

// ---------------- launch -------------------------------------------------------
static inline int cdiv(long long a, int b) { return (int)((a + b - 1) / b); }

extern "C" void kernel_launch(void* const* d_in, const int* in_sizes, int n_in,
                              void* d_out, int out_size) {
    const float* x    = (const float*)d_in[0];
    const float* W0p  = (const float*)d_in[1];
    const float* b0p  = (const float*)d_in[2];
    const float* W0n  = (const float*)d_in[3];
    const float* b0n  = (const float*)d_in[4];
    const float* W1p  = (const float*)d_in[5];
    const float* b1p  = (const float*)d_in[6];
    const float* W1n  = (const float*)d_in[7];
    const float* b1n  = (const float*)d_in[8];
    const float* Wc   = (const float*)d_in[9];
    const float* bc   = (const float*)d_in[10];
    const int*   srcp = (const int*)d_in[11];
    const int*   dstp = (const int*)d_in[12];
    const int*   srcn = (const int*)d_in[13];
    const int*   dstn = (const int*)d_in[14];
    const int*   ei   = (const int*)d_in[15];

    const int n   = in_sizes[0] / HH;
    const int nEp = in_sizes[11];
    const int nEn = in_sizes[13];
    const int nQ  = in_sizes[15] / 2;

    __half *x16, *w16, *y, *h;
    float *norms, *pbuf;
    int *cnt, *off, *rank, *csr, *flag, *pval, *ival;
    cudaGetSymbolAddress((void**)&x16,   g_x16);
    cudaGetSymbolAddress((void**)&w16,   g_w16);
    cudaGetSymbolAddress((void**)&y,     g_y);
    cudaGetSymbolAddress((void**)&h,     g_h);
    cudaGetSymbolAddress((void**)&norms, g_norms);
    cudaGetSymbolAddress((void**)&cnt,   g_cnt);
    cudaGetSymbolAddress((void**)&off,   g_off);
    cudaGetSymbolAddress((void**)&rank,  g_rank);
    cudaGetSymbolAddress((void**)&csr,   g_csr);
    cudaGetSymbolAddress((void**)&flag,  g_flag);
    cudaGetSymbolAddress((void**)&pval,  g_pval);
    cudaGetSymbolAddress((void**)&ival,  g_ival);
    cudaGetSymbolAddress((void**)&pbuf,  g_proj);

    float* z     = (float*)d_out;
    float* probs = (float*)d_out + (size_t)n * HH;

    const int nb    = cdiv(n, 1024);              // 98 (<=128)
    const int nx4   = n * 16;                     // float4 chunks of x
    const int gGemm = cdiv(n, 128);
    const int gScat = cdiv(nEp > nEn ? nEp : nEn, 1024);   // 4 edges/thread
    const int gEp   = cdiv(nEp, 1024);            // 4 edges/thread
    const int gEn   = cdiv(nEn, 1024);
    const int gX    = cdiv(nx4, 1024);            // 4 chunks/thread
    const int gAgg  = cdiv(n, 8);

    // 1) zero counts + lookback flags (tiny)
    zero_kernel<<<cdiv(n + 256, 256), 256>>>((int4*)cnt, flag, n);
    // 2) degrees/ranks (4 edges/thread) overlapped with x/W -> fp16 conversions
    deg_conv<<<2 * gEp + 2 * gEn + gX + 16, 256>>>(
        srcp, dstp, srcn, dstn, cnt, rank, x, x16,
        W0p, W0n, W1p, W1n, w16, n, nEp, nEn, gEp, gEn, gX, nx4);
    // 3) norms + CSR offsets in one launch (decoupled lookback)
    scan_lb_norm<<<dim3(nb, 4), 256>>>(cnt, norms, flag, pval, ival, off,
                                       n, nEp, nEn);
    // 4) layer-1 GEMM (tensor cores, fp16 W+X) + vectorized atomic-free scatter
    gemm1_scatter<<<2 * gGemm + 2 * gScat, 256>>>(
        x16, w16, norms, y, srcp, dstp, srcn, dstn, off, rank, csr,
        n, nEp, nEn, gGemm, gScat);
    // 5) layer-1 aggregation (both rels per warp, dual-stream) -> h (fp16)
    agg_l1<<<gAgg, 256>>>(y, off, csr, norms, b0p, b0n, h, n);
    // 6) layer-2 GEMM (fp16 input, tensor cores)
    gemm_l2<<<dim3(gGemm, 2), 256>>>(h, w16, norms, y, n);
    // 7) layer-2 aggregation (dual-stream) + combine + classifier projection
    agg_l2<<<gAgg, 256>>>(y, off, csr, norms, b1p, b1n, Wc, z, pbuf, n);
    // 8) classifier
    cls_kernel<<<cdiv(nQ, 256), 256>>>(pbuf, ei, bc, probs, nQ);
}

// round 16
// speedup vs baseline: 1.0807x; 1.0011x over previous
#include <cuda_runtime.h>
#include <cuda_fp16.h>
#include <mma.h>
#include <math.h>

using namespace nvcuda;

#define NN 100000
#define EE 1600000
#define HH 64
#define XS_LD 80   // padded smem stride (halves / floats)

typedef unsigned long long u64;

// ---------------- scratch (device globals) ----------------------------------
__device__ __half g_x16[(size_t)NN * HH];    // x converted to fp16
__device__ __half g_w16[4 * HH * HH];        // W0p|W0n|W1p|W1n in fp16
__device__ __half g_y[2 * (size_t)NN * HH];  // GEMM outputs (fp16)
__device__ __half g_h[2 * (size_t)NN * HH];  // layer-1 activations (fp16)
__device__ float  g_norms[4 * NN];           // csp | cdp | csn | cdn
__device__ int    g_cnt[4 * NN];             // int degree counts (same layout)
__device__ int    g_off[2 * (NN + 1)];       // CSR row offsets (dst) per relation
__device__ int    g_rank[2 * (size_t)EE];    // per-edge rank within dst bucket
__device__ int    g_csr[2 * EE];             // src ids grouped by dst
__device__ int    g_flag[2 * 128];           // lookback flags (0/1/2)
__device__ int    g_pval[2 * 128];           // block partial sums
__device__ int    g_ival[2 * 128];           // block inclusive prefixes
__device__ float  g_proj[4 * NN];            // classifier projections [N][4]

// ---------------- zero: counts + lookback flags (tiny, fast) -----------------
__global__ void zero_kernel(int4* __restrict__ cnt4, int* __restrict__ flag, int n) {
    int t = blockIdx.x * blockDim.x + threadIdx.x;
    if (t < n) cnt4[t] = make_int4(0, 0, 0, 0);
    else if (t < n + 256) flag[t - n] = 0;
}

// ---------------- fat kernel: degrees/ranks (4 edges/thread) + fp16 convs ----
__device__ __forceinline__ void deg_seg(const int* __restrict__ idx,
                                        int* __restrict__ cnt, int nE, int blk) {
    int e4 = (blk * 256 + threadIdx.x) * 4;
    if (e4 + 4 <= nE) {
        int4 v = *(const int4*)(idx + e4);
        atomicAdd(cnt + v.x, 1); atomicAdd(cnt + v.y, 1);
        atomicAdd(cnt + v.z, 1); atomicAdd(cnt + v.w, 1);
    } else {
        for (int e = e4; e < nE; e++) atomicAdd(cnt + idx[e], 1);
    }
}

__device__ __forceinline__ void rank_seg(const int* __restrict__ idx,
                                         int* __restrict__ cnt, int* __restrict__ rank,
                                         int nE, int blk) {
    int e4 = (blk * 256 + threadIdx.x) * 4;
    if (e4 + 4 <= nE) {
        int4 v = *(const int4*)(idx + e4);
        int4 r;
        r.x = atomicAdd(cnt + v.x, 1);
        r.y = atomicAdd(cnt + v.y, 1);
        r.z = atomicAdd(cnt + v.z, 1);
        r.w = atomicAdd(cnt + v.w, 1);
        *(int4*)(rank + e4) = r;
    } else {
        for (int e = e4; e < nE; e++) rank[e] = atomicAdd(cnt + idx[e], 1);
    }
}

__global__ void deg_conv(const int* __restrict__ sp, const int* __restrict__ dp,
                         const int* __restrict__ sn, const int* __restrict__ dn,
                         int* __restrict__ cnt, int* __restrict__ rank,
                         const float* __restrict__ x, __half* __restrict__ x16,
                         const float* __restrict__ W0p, const float* __restrict__ W0n,
                         const float* __restrict__ W1p, const float* __restrict__ W1n,
                         __half* __restrict__ w16,
                         int n, int nEp, int nEn, int gEp, int gEn, int gX, int nx4) {
    int b = blockIdx.x;
    if (b < gEp) { deg_seg(sp, cnt, nEp, b); return; }
    b -= gEp;
    if (b < gEp) { rank_seg(dp, cnt + (size_t)n, rank, nEp, b); return; }
    b -= gEp;
    if (b < gEn) { deg_seg(sn, cnt + 2 * (size_t)n, nEn, b); return; }
    b -= gEn;
    if (b < gEn) { rank_seg(dn, cnt + 3 * (size_t)n, rank + (size_t)EE, nEn, b); return; }
    b -= gEn;
    if (b < gX) {                        // x fp32 -> fp16, 4 float4 chunks/thread
        int c0 = (b * 256 + threadIdx.x) * 4;
        #pragma unroll
        for (int j = 0; j < 4; j++) {
            int c = c0 + j;
            if (c < nx4) {
                float4 v = ((const float4*)x)[c];
                __half2 h[2] = {__floats2half2_rn(v.x, v.y),
                                __floats2half2_rn(v.z, v.w)};
                ((uint2*)x16)[c] = *(const uint2*)h;
            }
        }
        return;
    }
    b -= gX;
    {                                    // W fp32 -> fp16 (16 blocks)
        int c = b * 256 + threadIdx.x;   // 4096 float4 chunks total
        if (c < 4096) {
            int m = c >> 10, i = c & 1023;
            const float* W = (m == 0) ? W0p : (m == 1) ? W0n : (m == 2) ? W1p : W1n;
            float4 v = ((const float4*)W)[i];
            __half2 h[2] = {__floats2half2_rn(v.x, v.y), __floats2half2_rn(v.z, v.w)};
            ((uint2*)w16)[c] = *(const uint2*)h;
        }
    }
}

// ---------------- one-launch scan: norms (all 4) + CSR offsets (lookback) ----
__global__ void scan_lb_norm(const int* __restrict__ cnt, float* __restrict__ norms,
                             volatile int* flag, volatile int* pval, volatile int* ival,
                             int* __restrict__ offv, int n, int nEp, int nEn) {
    int w = blockIdx.y;                 // 0..3
    int bx = blockIdx.x;
    int tid = threadIdx.x;
    const int* c = cnt + (size_t)w * n;
    float* nm = norms + (size_t)w * n;
    int base = bx * 1024 + tid * 4;

    int v[4], s = 0;
    #pragma unroll
    for (int j = 0; j < 4; j++) {
        int i = base + j;
        v[j] = (i < n) ? c[i] : 0;
        s += v[j];
        if (i < n) nm[i] = (v[j] > 0) ? rsqrtf((float)v[j]) : 0.f;
    }
    if (!(w & 1)) return;               // only dst arrays build CSR
    int rel = w >> 1;
    int sbase = rel * 128;

    __shared__ int sm[256];
    sm[tid] = s; __syncthreads();
    for (int ofs = 1; ofs < 256; ofs <<= 1) {
        int a = (tid >= ofs) ? sm[tid - ofs] : 0;
        __syncthreads();
        sm[tid] += a;
        __syncthreads();
    }
    int excl = sm[tid] - s;
    int bsum = sm[255];

    __shared__ int bprefix;
    if (tid == 0) {
        pval[sbase + bx] = bsum;
        __threadfence();
        flag[sbase + bx] = 1;
        int pref = 0;
        for (int p = bx - 1; p >= 0; ) {
            int f;
            do { f = flag[sbase + p]; } while (f == 0);
            if (f == 2) { pref += ival[sbase + p]; break; }
            pref += pval[sbase + p];
            p--;
        }
        ival[sbase + bx] = pref + bsum;
        __threadfence();
        flag[sbase + bx] = 2;
        bprefix = pref;
    }
    __syncthreads();

    int ex = bprefix + excl;
    int* o = offv + (size_t)rel * (n + 1);
    #pragma unroll
    for (int j = 0; j < 4; j++) {
        int i = base + j;
        if (i < n) o[i] = ex;
        ex += v[j];
    }
    if (bx == 0 && tid == 0) o[n] = rel ? nEn : nEp;
}

// ---------------- wmma GEMM body (fp16 X and W), smem union (40 KB) ----------
__device__ __forceinline__ void gemm_body(const __half* __restrict__ X,
                                          const float* __restrict__ cs,
                                          const __half* __restrict__ W16,
                                          __half* __restrict__ Yo, int n, int blk) {
    __shared__ __align__(16) float sbuf[128 * XS_LD];   // 40960 B
    __half* Wh = (__half*)sbuf;
    __half* Xh = ((__half*)sbuf) + 64 * XS_LD;
    float*  Os = sbuf;                                  // reused after MMA

    int tid = threadIdx.x;
    int row0 = blk * 128;

    for (int i = tid; i < 1024; i += 256) {             // W: raw fp16 copy
        int k = i >> 4, j = i & 15;
        *(uint2*)&Wh[k * XS_LD + 4 * j] = ((const uint2*)W16)[(size_t)k * 16 + j];
    }
    for (int i = tid; i < 2048; i += 256) {
        int r = i >> 4, kq = i & 15;
        int gr = row0 + r;
        uint2 v2 = (gr < n) ? __ldg((const uint2*)X + (size_t)gr * 16 + kq)
                            : make_uint2(0, 0);
        *(uint2*)&Xh[r * XS_LD + 4 * kq] = v2;
    }
    __syncthreads();

    int w = tid >> 5;
    wmma::fragment<wmma::accumulator, 16, 16, 16, float> acc[4];
    #pragma unroll
    for (int t = 0; t < 4; t++) wmma::fill_fragment(acc[t], 0.f);
    #pragma unroll
    for (int k = 0; k < 64; k += 16) {
        wmma::fragment<wmma::matrix_a, 16, 16, 16, __half, wmma::row_major> a;
        wmma::load_matrix_sync(a, &Xh[(w * 16) * XS_LD + k], XS_LD);
        #pragma unroll
        for (int t = 0; t < 4; t++) {
            wmma::fragment<wmma::matrix_b, 16, 16, 16, __half, wmma::row_major> b;
            wmma::load_matrix_sync(b, &Wh[k * XS_LD + t * 16], XS_LD);
            wmma::mma_sync(acc[t], a, b, acc[t]);
        }
    }
    __syncthreads();             // all reads of Wh/Xh done; Os may overwrite
    #pragma unroll
    for (int t = 0; t < 4; t++)
        wmma::store_matrix_sync(&Os[(w * 16) * XS_LD + t * 16], acc[t], XS_LD,
                                wmma::mem_row_major);
    __syncthreads();

    for (int i = tid; i < 2048; i += 256) {
        int r = i >> 4, q = i & 15;
        int gr = row0 + r;
        if (gr >= n) continue;
        float c = cs[gr];
        float4 v = *(const float4*)&Os[r * XS_LD + 4 * q];
        __half2 o[2] = {__floats2half2_rn(v.x * c, v.y * c),
                        __floats2half2_rn(v.z * c, v.w * c)};
        *(uint2*)(Yo + (size_t)gr * 64 + 4 * q) = *(const uint2*)o;
    }
}

// ---------------- fat kernel: layer-1 GEMM (both rels) + vectorized scatter --
__global__ void __launch_bounds__(256, 4)
gemm1_scatter(const __half* __restrict__ x16, const __half* __restrict__ w16,
              const float* __restrict__ norms, __half* __restrict__ Y,
              const int* __restrict__ srcp, const int* __restrict__ dstp,
              const int* __restrict__ srcn, const int* __restrict__ dstn,
              const int* __restrict__ off, const int* __restrict__ rank,
              int* __restrict__ csr,
              int n, int nEp, int nEn, int gGemm, int gScat) {
    int b = blockIdx.x;
    if (b < 2 * gGemm) {
        int rel = b / gGemm;
        gemm_body(x16, norms + 2 * (size_t)rel * n, w16 + (size_t)rel * 4096,
                  Y + (size_t)rel * n * 64, n, b % gGemm);
    } else {
        int sb = b - 2 * gGemm;
        int rel = sb / gScat;
        int e4 = ((sb % gScat) * 256 + threadIdx.x) * 4;   // 4 edges per thread
        int nE = rel ? nEn : nEp;
        if (e4 >= nE) return;
        const int* src = rel ? srcn : srcp;
        const int* dst = rel ? dstn : dstp;
        const int* ofr = off + (size_t)rel * (n + 1);
        const int* rk  = rank + (size_t)rel * EE;
        int* cs_ = csr + (size_t)rel * EE;
        if (e4 + 4 <= nE) {
            int4 d4 = *(const int4*)(dst + e4);
            int4 r4 = *(const int4*)(rk + e4);
            int4 s4 = *(const int4*)(src + e4);
            cs_[__ldg(ofr + d4.x) + r4.x] = s4.x;
            cs_[__ldg(ofr + d4.y) + r4.y] = s4.y;
            cs_[__ldg(ofr + d4.z) + r4.z] = s4.z;
            cs_[__ldg(ofr + d4.w) + r4.w] = s4.w;
        } else {
            for (int e = e4; e < nE; e++)
                cs_[__ldg(ofr + dst[e]) + rk[e]] = src[e];
        }
    }
}

// ---------------- layer-2 GEMM (fp16 input) ----------------------------------
__global__ void __launch_bounds__(256, 4)
gemm_l2(const __half* __restrict__ h, const __half* __restrict__ w16,
        const float* __restrict__ norms, __half* __restrict__ Y, int n) {
    int rel = blockIdx.y;
    gemm_body(h + (size_t)rel * n * 64, norms + 2 * (size_t)rel * n,
              w16 + (2 + (size_t)rel) * 4096, Y + (size_t)rel * n * 64, n, blockIdx.x);
}

// ---------------- dual-stream CSR pull with coalesced idx loads --------------
// Main loop: lanes (lane&3) cooperatively load 4 consecutive csr entries in ONE
// coalesced LDG (1 sector vs 4 broadcast sectors), redistributed via shfl.
__device__ __forceinline__ void csr_sum_dual(
    const int* __restrict__ off0, const int* __restrict__ csr0,
    const __half2* __restrict__ yl0,
    const int* __restrict__ off1, const int* __restrict__ csr1,
    const __half2* __restrict__ yl1,
    int node, int lane, float2& r0, float2& r1) {
    int j0 = __ldg(off0 + node), e0 = __ldg(off0 + node + 1);
    int j1 = __ldg(off1 + node), e1 = __ldg(off1 + node + 1);
    float2 a00 = make_float2(0.f, 0.f), a01 = make_float2(0.f, 0.f);
    float2 a10 = make_float2(0.f, 0.f), a11 = make_float2(0.f, 0.f);
    int l4 = lane & 3;

    // main loop: 8 edges per iter (4 per stream), 2 coalesced idx LDGs
    while (j0 + 4 <= e0 && j1 + 4 <= e1) {
        int m0 = __ldg(csr0 + j0 + l4);
        int m1 = __ldg(csr1 + j1 + l4);
        int s00 = __shfl_sync(0xffffffffu, m0, 0, 4);
        int s01 = __shfl_sync(0xffffffffu, m0, 1, 4);
        int s02 = __shfl_sync(0xffffffffu, m0, 2, 4);
        int s03 = __shfl_sync(0xffffffffu, m0, 3, 4);
        int s10 = __shfl_sync(0xffffffffu, m1, 0, 4);
        int s11 = __shfl_sync(0xffffffffu, m1, 1, 4);
        int s12 = __shfl_sync(0xffffffffu, m1, 2, 4);
        int s13 = __shfl_sync(0xffffffffu, m1, 3, 4);
        __half2 hA = __ldg(yl0 + (size_t)s00 * 32);
        __half2 hB = __ldg(yl0 + (size_t)s01 * 32);
        __half2 hC = __ldg(yl0 + (size_t)s02 * 32);
        __half2 hD = __ldg(yl0 + (size_t)s03 * 32);
        __half2 hE = __ldg(yl1 + (size_t)s10 * 32);
        __half2 hF = __ldg(yl1 + (size_t)s11 * 32);
        __half2 hG = __ldg(yl1 + (size_t)s12 * 32);
        __half2 hH = __ldg(yl1 + (size_t)s13 * 32);
        float2 v;
        v = __half22float2(hA); a00.x += v.x; a00.y += v.y;
        v = __half22float2(hB); a01.x += v.x; a01.y += v.y;
        v = __half22float2(hC); a00.x += v.x; a00.y += v.y;
        v = __half22float2(hD); a01.x += v.x; a01.y += v.y;
        v = __half22float2(hE); a10.x += v.x; a10.y += v.y;
        v = __half22float2(hF); a11.x += v.x; a11.y += v.y;
        v = __half22float2(hG); a10.x += v.x; a10.y += v.y;
        v = __half22float2(hH); a11.x += v.x; a11.y += v.y;
        j0 += 4; j1 += 4;
    }
    // drain stream 0 (2-way)
    for (; j0 + 2 <= e0; j0 += 2) {
        int sA = __ldg(csr0 + j0);
        int sB = __ldg(csr0 + j0 + 1);
        __half2 hA = __ldg(yl0 + (size_t)sA * 32);
        __half2 hB = __ldg(yl0 + (size_t)sB * 32);
        float2 vA = __half22float2(hA); a00.x += vA.x; a00.y += vA.y;
        float2 vB = __half22float2(hB); a01.x += vB.x; a01.y += vB.y;
    }
    if (j0 < e0) {
        int sA = __ldg(csr0 + j0);
        float2 vA = __half22float2(__ldg(yl0 + (size_t)sA * 32));
        a00.x += vA.x; a00.y += vA.y;
    }
    // drain stream 1 (2-way)
    for (; j1 + 2 <= e1; j1 += 2) {
        int sC = __ldg(csr1 + j1);
        int sD = __ldg(csr1 + j1 + 1);
        __half2 hC = __ldg(yl1 + (size_t)sC * 32);
        __half2 hD = __ldg(yl1 + (size_t)sD * 32);
        float2 vC = __half22float2(hC); a10.x += vC.x; a10.y += vC.y;
        float2 vD = __half22float2(hD); a11.x += vD.x; a11.y += vD.y;
    }
    if (j1 < e1) {
        int sC = __ldg(csr1 + j1);
        float2 vC = __half22float2(__ldg(yl1 + (size_t)sC * 32));
        a10.x += vC.x; a10.y += vC.y;
    }
    r0 = make_float2(a00.x + a01.x, a00.y + a01.y);
    r1 = make_float2(a10.x + a11.x, a10.y + a11.y);
}

// layer 1, both relations per warp: h_rel[i,:] = half(relu(c_dst * sum + b0))
__global__ void agg_l1(const __half* __restrict__ y, const int* __restrict__ off,
                       const int* __restrict__ csr, const float* __restrict__ norms,
                       const float* __restrict__ b0p, const float* __restrict__ b0n,
                       __half* __restrict__ h, int n) {
    int node = blockIdx.x * 8 + (threadIdx.x >> 5);
    if (node >= n) return;
    int lane = threadIdx.x & 31;
    const __half2* yl0 = (const __half2*)y + lane;
    const __half2* yl1 = (const __half2*)(y + (size_t)n * 64) + lane;
    float2 aP, aN;
    csr_sum_dual(off, csr, yl0, off + (n + 1), csr + (size_t)EE, yl1, node, lane, aP, aN);
    float c0 = norms[(size_t)n + node];
    float c1 = norms[3 * (size_t)n + node];
    float2 bp = *(const float2*)(b0p + 2 * lane);
    float2 bn = *(const float2*)(b0n + 2 * lane);
    ((__half2*)(h + (size_t)node * 64))[lane] =
        __floats2half2_rn(fmaxf(c0 * aP.x + bp.x, 0.f), fmaxf(c0 * aP.y + bp.y, 0.f));
    ((__half2*)(h + ((size_t)n + node) * 64))[lane] =
        __floats2half2_rn(fmaxf(c1 * aN.x + bn.x, 0.f), fmaxf(c1 * aN.y + bn.y, 0.f));
}

// layer 2: z = relu(cdp*sumP + b1p) - relu(cdn*sumN + b1n) + fused projection
__global__ void agg_l2(const __half* __restrict__ y, const int* __restrict__ off,
                       const int* __restrict__ csr, const float* __restrict__ norms,
                       const float* __restrict__ b1p, const float* __restrict__ b1n,
                       const float* __restrict__ Wc,
                       float* __restrict__ z, float* __restrict__ proj, int n) {
    __shared__ float Wcs[256];
    Wcs[threadIdx.x] = Wc[threadIdx.x];   // blockDim == 256
    __syncthreads();

    int node = blockIdx.x * 8 + (threadIdx.x >> 5);
    if (node >= n) return;
    int lane = threadIdx.x & 31;
    const __half2* yl0 = (const __half2*)y + lane;
    const __half2* yl1 = (const __half2*)(y + (size_t)n * 64) + lane;
    float2 aP, aN;
    csr_sum_dual(off, csr, yl0, off + (n + 1), csr + (size_t)EE, yl1, node, lane, aP, aN);
    float cp = norms[(size_t)n + node];
    float cn = norms[3 * (size_t)n + node];
    float2 r;
    r.x = fmaxf(cp * aP.x + b1p[2 * lane + 0], 0.f) - fmaxf(cn * aN.x + b1n[2 * lane + 0], 0.f);
    r.y = fmaxf(cp * aP.y + b1p[2 * lane + 1], 0.f) - fmaxf(cn * aN.y + b1n[2 * lane + 1], 0.f);
    *(float2*)(z + (size_t)node * 64 + lane * 2) = r;

    int k = 2 * lane;
    float s0 = r.x * Wcs[k * 2 + 0] + r.y * Wcs[(k + 1) * 2 + 0];
    float s1 = r.x * Wcs[k * 2 + 1] + r.y * Wcs[(k + 1) * 2 + 1];
    float d0 = r.x * Wcs[128 + k * 2 + 0] + r.y * Wcs[128 + (k + 1) * 2 + 0];
    float d1 = r.x * Wcs[128 + k * 2 + 1] + r.y * Wcs[128 + (k + 1) * 2 + 1];
    #pragma unroll
    for (int o = 16; o > 0; o >>= 1) {
        s0 += __shfl_xor_sync(0xffffffffu, s0, o);
        s1 += __shfl_xor_sync(0xffffffffu, s1, o);
        d0 += __shfl_xor_sync(0xffffffffu, d0, o);
        d1 += __shfl_xor_sync(0xffffffffu, d1, o);
    }
    if (lane == 0) ((float4*)proj)[node] = make_float4(s0, s1, d0, d1);
}

// ---------------- classifier --------------------------------------------------
__global__ void cls_kernel(const float* __restrict__ p, const int* __restrict__ ei,
                           const float* __restrict__ bc, float* __restrict__ out, int nQ) {
    int q = blockIdx.x * blockDim.x + threadIdx.x;
    if (q >= nQ) return;
    int s = __ldg(ei + q);
    int d = __ldg(ei + nQ + q);
    float4 ps = ((const float4*)p)[s];
    float4 pd = ((const float4*)p)[d];
    float l0 = ps.x + pd.z + bc[0];
    float l1 = ps.y + pd.w + bc[1];
    float2 o;
    o.x = 1.f / (1.f + __expf(-l0));
    o.y = 1.f / (1.f + __expf(-l1));
    ((float2*)out)[q] = o;
}

// ---------------- launch -------------------------------------------------------
static inline int cdiv(long long a, int b) { return (int)((a + b - 1) / b); }

extern "C" void kernel_launch(void* const* d_in, const int* in_sizes, int n_in,
                              void* d_out, int out_size) {
    const float* x    = (const float*)d_in[0];
    const float* W0p  = (const float*)d_in[1];
    const float* b0p  = (const float*)d_in[2];
    const float* W0n  = (const float*)d_in[3];
    const float* b0n  = (const float*)d_in[4];
    const float* W1p  = (const float*)d_in[5];
    const float* b1p  = (const float*)d_in[6];
    const float* W1n  = (const float*)d_in[7];
    const float* b1n  = (const float*)d_in[8];
    const float* Wc   = (const float*)d_in[9];
    const float* bc   = (const float*)d_in[10];
    const int*   srcp = (const int*)d_in[11];
    const int*   dstp = (const int*)d_in[12];
    const int*   srcn = (const int*)d_in[13];
    const int*   dstn = (const int*)d_in[14];
    const int*   ei   = (const int*)d_in[15];

    const int n   = in_sizes[0] / HH;
    const int nEp = in_sizes[11];
    const int nEn = in_sizes[13];
    const int nQ  = in_sizes[15] / 2;

    __half *x16, *w16, *y, *h;
    float *norms, *pbuf;
    int *cnt, *off, *rank, *csr, *flag, *pval, *ival;
    cudaGetSymbolAddress((void**)&x16,   g_x16);
    cudaGetSymbolAddress((void**)&w16,   g_w16);
    cudaGetSymbolAddress((void**)&y,     g_y);
    cudaGetSymbolAddress((void**)&h,     g_h);
    cudaGetSymbolAddress((void**)&norms, g_norms);
    cudaGetSymbolAddress((void**)&cnt,   g_cnt);
    cudaGetSymbolAddress((void**)&off,   g_off);
    cudaGetSymbolAddress((void**)&rank,  g_rank);
    cudaGetSymbolAddress((void**)&csr,   g_csr);
    cudaGetSymbolAddress((void**)&flag,  g_flag);
    cudaGetSymbolAddress((void**)&pval,  g_pval);
    cudaGetSymbolAddress((void**)&ival,  g_ival);
    cudaGetSymbolAddress((void**)&pbuf,  g_proj);

    float* z     = (float*)d_out;
    float* probs = (float*)d_out + (size_t)n * HH;

    const int nb    = cdiv(n, 1024);              // 98 (<=128)
    const int nx4   = n * 16;                     // float4 chunks of x
    const int gGemm = cdiv(n, 128);
    const int gScat = cdiv(nEp > nEn ? nEp : nEn, 1024);   // 4 edges/thread
    const int gEp   = cdiv(nEp, 1024);            // 4 edges/thread
    const int gEn   = cdiv(nEn, 1024);
    const int gX    = cdiv(nx4, 1024);            // 4 chunks/thread
    const int gAgg  = cdiv(n, 8);

    // 1) zero counts + lookback flags (tiny)
    zero_kernel<<<cdiv(n + 256, 256), 256>>>((int4*)cnt, flag, n);
    // 2) degrees/ranks (4 edges/thread) overlapped with x/W -> fp16 conversions
    deg_conv<<<2 * gEp + 2 * gEn + gX + 16, 256>>>(
        srcp, dstp, srcn, dstn, cnt, rank, x, x16,
        W0p, W0n, W1p, W1n, w16, n, nEp, nEn, gEp, gEn, gX, nx4);
    // 3) norms + CSR offsets in one launch (decoupled lookback)
    scan_lb_norm<<<dim3(nb, 4), 256>>>(cnt, norms, flag, pval, ival, off,
                                       n, nEp, nEn);
    // 4) layer-1 GEMM (tensor cores, fp16 W+X) + vectorized atomic-free scatter
    gemm1_scatter<<<2 * gGemm + 2 * gScat, 256>>>(
        x16, w16, norms, y, srcp, dstp, srcn, dstn, off, rank, csr,
        n, nEp, nEn, gGemm, gScat);
    // 5) layer-1 aggregation (dual-stream, coalesced idx) -> h (fp16)
    agg_l1<<<gAgg, 256>>>(y, off, csr, norms, b0p, b0n, h, n);
    // 6) layer-2 GEMM (fp16 input, tensor cores)
    gemm_l2<<<dim3(gGemm, 2), 256>>>(h, w16, norms, y, n);
    // 7) layer-2 aggregation (dual-stream, coalesced idx) + combine + projection
    agg_l2<<<gAgg, 256>>>(y, off, csr, norms, b1p, b1n, Wc, z, pbuf, n);
    // 8) classifier
    cls_kernel<<<cdiv(nQ, 256), 256>>>(pbuf, ei, bc, probs, nQ);
}